// round 1
// baseline (speedup 1.0000x reference)
#include <cuda_runtime.h>

#define NN 50000
#define EE 500000
#define FIN 388

// ---------------- static scratch (no allocation allowed) ----------------
__device__ float    g_xl1[(size_t)NN*512];
__device__ float    g_xr1[(size_t)NN*512];
__device__ float    g_h1 [(size_t)NN*512];
__device__ float    g_xl2[(size_t)NN*1024];
__device__ float    g_xr2[(size_t)NN*1024];
__device__ float    g_agg[(size_t)NN*1024];
__device__ float    g_h2 [(size_t)NN*128];
__device__ float    g_score[(size_t)(EE+NN)*8];
__device__ unsigned g_smax[(size_t)NN*8];
__device__ float    g_denom[(size_t)NN*8];
__device__ float    g_deg[NN];
__device__ float    g_loopsum[(size_t)NN*16];
__device__ float    g_loopattr[(size_t)NN*16];
__device__ float    g_Wet1[512*16];
__device__ float    g_Wet2[1024*16];

// monotonic float <-> uint mapping for atomicMax on floats (any sign)
__device__ __forceinline__ unsigned fkey(float f){
    unsigned u = __float_as_uint(f);
    return (u & 0x80000000u) ? ~u : (u | 0x80000000u);
}
__device__ __forceinline__ float funkey(unsigned u){
    return (u & 0x80000000u) ? __uint_as_float(u & 0x7fffffffu) : __uint_as_float(~u);
}

// ---------------- self-loop attr (mean of incoming edge_attr) ----------------
__global__ void k_deg(const int* __restrict__ ei, const float* __restrict__ ea){
    int t = blockIdx.x * blockDim.x + threadIdx.x;
    if (t >= EE*16) return;
    int e = t >> 4, k = t & 15;
    int dst = ei[EE + e];
    atomicAdd(&g_loopsum[dst*16 + k], ea[t]);
    if (k == 0) atomicAdd(&g_deg[dst], 1.0f);
}

__global__ void k_loopattr(){
    int t = blockIdx.x * blockDim.x + threadIdx.x;
    if (t >= NN*16) return;
    g_loopattr[t] = g_loopsum[t] / fmaxf(g_deg[t >> 4], 1.0f);
}

// transpose We [16, HD] -> Wet [HD, 16] so edge kernels can float4-load it
__global__ void k_transpose(const float* __restrict__ We, float* __restrict__ Wet, int HD){
    int t = blockIdx.x * blockDim.x + threadIdx.x;
    if (t >= 16*HD) return;
    int k = t / HD, j = t % HD;
    Wet[j*16 + k] = We[t];
}

// ---------------- tiled SGEMM: C[M,N] = A[M,K] @ B[K,N], row-major ----------------
// BM=BN=128, BK=8, 256 threads, 8x8 microtile. N % 128 == 0, K % 4 == 0 here.
__global__ void k_sgemm(const float* __restrict__ A, const float* __restrict__ B,
                        float* __restrict__ C, int M, int N, int K)
{
    __shared__ float As[8][128];
    __shared__ float Bs[8][128];
    int tid = threadIdx.x;
    int bm = blockIdx.y * 128;
    int bn = blockIdx.x * 128;

    int arow = tid >> 1;            // 0..127
    int acol = (tid & 1) * 4;       // 0 or 4
    int brow = tid >> 5;            // 0..7
    int bcol = (tid & 31) * 4;      // 0..124

    int tr = (tid >> 4) * 8;        // 0..120
    int tc = (tid & 15) * 8;        // 0..120

    float acc[8][8];
    #pragma unroll
    for (int i = 0; i < 8; i++)
        #pragma unroll
        for (int j = 0; j < 8; j++) acc[i][j] = 0.f;

    for (int k0 = 0; k0 < K; k0 += 8) {
        float4 av = make_float4(0.f, 0.f, 0.f, 0.f);
        int gm = bm + arow;
        if (gm < M && (k0 + acol + 4) <= K)
            av = *(const float4*)(A + (size_t)gm * K + k0 + acol);
        As[acol + 0][arow] = av.x;
        As[acol + 1][arow] = av.y;
        As[acol + 2][arow] = av.z;
        As[acol + 3][arow] = av.w;

        float4 bv = make_float4(0.f, 0.f, 0.f, 0.f);
        int gk = k0 + brow;
        if (gk < K)
            bv = *(const float4*)(B + (size_t)gk * N + bn + bcol);
        *(float4*)&Bs[brow][bcol] = bv;

        __syncthreads();
        #pragma unroll
        for (int kk = 0; kk < 8; kk++) {
            float4 ra0 = *(const float4*)&As[kk][tr];
            float4 ra1 = *(const float4*)&As[kk][tr + 4];
            float4 rb0 = *(const float4*)&Bs[kk][tc];
            float4 rb1 = *(const float4*)&Bs[kk][tc + 4];
            float ra[8] = {ra0.x, ra0.y, ra0.z, ra0.w, ra1.x, ra1.y, ra1.z, ra1.w};
            float rb[8] = {rb0.x, rb0.y, rb0.z, rb0.w, rb1.x, rb1.y, rb1.z, rb1.w};
            #pragma unroll
            for (int i = 0; i < 8; i++)
                #pragma unroll
                for (int j = 0; j < 8; j++)
                    acc[i][j] += ra[i] * rb[j];
        }
        __syncthreads();
    }

    #pragma unroll
    for (int i = 0; i < 8; i++) {
        int gm = bm + tr + i;
        if (gm < M) {
            #pragma unroll
            for (int j = 0; j < 8; j += 4) {
                *(float4*)(C + (size_t)gm * N + bn + tc + j) =
                    make_float4(acc[i][j], acc[i][j+1], acc[i][j+2], acc[i][j+3]);
            }
        }
    }
}

// ---------------- edge scores: warp per edge (incl. self-loops at E..E+N) ----------------
template<int HD, int D>
__global__ void k_score(const int* __restrict__ ei, const float* __restrict__ eattr,
                        const float* __restrict__ xl, const float* __restrict__ xr,
                        const float* __restrict__ Wet, const float* __restrict__ att)
{
    int gw = (blockIdx.x * blockDim.x + threadIdx.x) >> 5;
    int lane = threadIdx.x & 31;
    if (gw >= EE + NN) return;
    int src, dst; const float* ea;
    if (gw < EE) { src = ei[gw]; dst = ei[EE + gw]; ea = eattr + (size_t)gw * 16; }
    else         { src = gw - EE; dst = src;        ea = g_loopattr + (size_t)src * 16; }

    float4 a0 = ((const float4*)ea)[0];
    float4 a1 = ((const float4*)ea)[1];
    float4 a2 = ((const float4*)ea)[2];
    float4 a3 = ((const float4*)ea)[3];

    const float* xls = xl + (size_t)src * HD;
    const float* xrd = xr + (size_t)dst * HD;
    constexpr int CPH = D / 32;   // c-iterations per head

    float myscore = 0.f;
    #pragma unroll
    for (int h = 0; h < 8; h++) {
        float ph = 0.f;
        #pragma unroll
        for (int cc = 0; cc < CPH; cc++) {
            int c = h * CPH + cc;
            int j = c * 32 + lane;
            const float4* wr = (const float4*)(Wet + (size_t)j * 16);
            float4 w0 = wr[0], w1 = wr[1], w2 = wr[2], w3 = wr[3];
            float ee = a0.x*w0.x + a0.y*w0.y + a0.z*w0.z + a0.w*w0.w
                     + a1.x*w1.x + a1.y*w1.y + a1.z*w1.z + a1.w*w1.w
                     + a2.x*w2.x + a2.y*w2.y + a2.z*w2.z + a2.w*w2.w
                     + a3.x*w3.x + a3.y*w3.y + a3.z*w3.z + a3.w*w3.w;
            float v = xls[j] + xrd[j] + ee;
            v = v > 0.f ? v : 0.2f * v;          // leaky_relu(., 0.2)
            ph += att[j] * v;                     // att[h*D+d] == att[j]
        }
        float s = ph;
        #pragma unroll
        for (int off = 16; off > 0; off >>= 1)
            s += __shfl_xor_sync(0xffffffffu, s, off);
        if (lane == h) myscore = s;
    }
    if (lane < 8) {
        g_score[(size_t)gw * 8 + lane] = myscore;
        atomicMax(&g_smax[dst * 8 + lane], fkey(myscore));
    }
}

// ---------------- fused exp + denom + weighted aggregation ----------------
template<int HD, int D>
__global__ void k_agg(const int* __restrict__ ei, const float* __restrict__ xl)
{
    int gw = (blockIdx.x * blockDim.x + threadIdx.x) >> 5;
    int lane = threadIdx.x & 31;
    if (gw >= EE + NN) return;
    int src, dst;
    if (gw < EE) { src = ei[gw]; dst = ei[EE + gw]; }
    else         { src = gw - EE; dst = src; }

    float w8 = 0.f;
    if (lane < 8) {
        float s = g_score[(size_t)gw * 8 + lane];
        float m = funkey(g_smax[dst * 8 + lane]);
        w8 = __expf(s - m);
        atomicAdd(&g_denom[dst * 8 + lane], w8);
    }
    const float* xls = xl + (size_t)src * HD;
    float* ag = g_agg + (size_t)dst * HD;
    constexpr int CPH = D / 32;
    #pragma unroll
    for (int c = 0; c < HD/32; c++) {
        float w = __shfl_sync(0xffffffffu, w8, c / CPH);
        int j = c * 32 + lane;
        atomicAdd(&ag[j], w * xls[j]);
    }
}

// ---------------- layer finalization ----------------
__global__ void k_fin1(const float* __restrict__ b1){
    int t = blockIdx.x * blockDim.x + threadIdx.x;
    if (t >= NN*512) return;
    int n = t >> 9, j = t & 511, h = j >> 6;
    g_h1[t] = tanhf(g_agg[t] / g_denom[n*8 + h] + b1[j]);
}

__global__ void k_fin2(const float* __restrict__ b2){
    int t = blockIdx.x * blockDim.x + threadIdx.x;
    if (t >= NN*128) return;
    int n = t >> 7, d = t & 127;
    float s = 0.f;
    #pragma unroll
    for (int h = 0; h < 8; h++)
        s += g_agg[(size_t)n*1024 + h*128 + d] / g_denom[n*8 + h];
    g_h2[t] = tanhf(s * 0.125f + b2[d]);
}

// ---------------- single-step LSTM (h0=c0=0) + FC: warp per node ----------------
__global__ void k_lstm(const float* __restrict__ W_ih, const float* __restrict__ b_ih,
                       const float* __restrict__ b_hh, const float* __restrict__ fcW,
                       const float* __restrict__ fcb, float* __restrict__ out)
{
    __shared__ float sh[8][128];
    int w = threadIdx.x >> 5, lane = threadIdx.x & 31;
    int node = blockIdx.x * 8 + w;
    if (node >= NN) return;
    const float* hr = g_h2 + (size_t)node * 128;
    for (int i = lane; i < 128; i += 32) sh[w][i] = hr[i];
    __syncwarp();

    // gate rows needed: i = lane, g = 64+lane, o = 96+lane  (f unused: c0 = 0)
    float gates[3];
    const int rows[3] = {lane, 64 + lane, 96 + lane};
    #pragma unroll
    for (int q = 0; q < 3; q++) {
        const float4* wr = (const float4*)(W_ih + (size_t)rows[q] * 128);
        const float4* hv = (const float4*)sh[w];
        float s = 0.f;
        #pragma unroll 8
        for (int k = 0; k < 32; k++) {
            float4 wv = wr[k], xv = hv[k];
            s += wv.x*xv.x + wv.y*xv.y + wv.z*xv.z + wv.w*xv.w;
        }
        gates[q] = s + b_ih[rows[q]] + b_hh[rows[q]];
    }
    float ci = 1.f / (1.f + __expf(-gates[0]));
    float cg = tanhf(gates[1]);
    float co = 1.f / (1.f + __expf(-gates[2]));
    float c  = ci * cg;
    float hid = co * tanhf(c);
    float y = hid * fcW[lane];
    #pragma unroll
    for (int off = 16; off > 0; off >>= 1)
        y += __shfl_xor_sync(0xffffffffu, y, off);
    if (lane == 0) out[node] = y + fcb[0];
}

// ---------------- launch ----------------
extern "C" void kernel_launch(void* const* d_in, const int* in_sizes, int n_in,
                              void* d_out, int out_size)
{
    const float* x    = (const float*)d_in[0];
    const int*   ei   = (const int*)  d_in[1];
    const float* ea   = (const float*)d_in[2];
    const float* Wl1  = (const float*)d_in[3];
    const float* Wr1  = (const float*)d_in[4];
    const float* We1  = (const float*)d_in[5];
    const float* att1 = (const float*)d_in[6];
    const float* b1   = (const float*)d_in[7];
    const float* Wl2  = (const float*)d_in[8];
    const float* Wr2  = (const float*)d_in[9];
    const float* We2  = (const float*)d_in[10];
    const float* att2 = (const float*)d_in[11];
    const float* b2   = (const float*)d_in[12];
    const float* W_ih = (const float*)d_in[13];
    /* d_in[14] = W_hh: unused (h0 = 0) */
    const float* b_ih = (const float*)d_in[15];
    const float* b_hh = (const float*)d_in[16];
    const float* fcW  = (const float*)d_in[17];
    const float* fcb  = (const float*)d_in[18];
    float* out = (float*)d_out;

    void* p;
    float *xl1, *xr1, *xl2, *xr2, *h1, *agg, *denom, *deg, *loopsum, *Wet1, *Wet2;
    unsigned* smax;
    cudaGetSymbolAddress(&p, g_xl1);     xl1     = (float*)p;
    cudaGetSymbolAddress(&p, g_xr1);     xr1     = (float*)p;
    cudaGetSymbolAddress(&p, g_xl2);     xl2     = (float*)p;
    cudaGetSymbolAddress(&p, g_xr2);     xr2     = (float*)p;
    cudaGetSymbolAddress(&p, g_h1);      h1      = (float*)p;
    cudaGetSymbolAddress(&p, g_agg);     agg     = (float*)p;
    cudaGetSymbolAddress(&p, g_denom);   denom   = (float*)p;
    cudaGetSymbolAddress(&p, g_deg);     deg     = (float*)p;
    cudaGetSymbolAddress(&p, g_loopsum); loopsum = (float*)p;
    cudaGetSymbolAddress(&p, g_Wet1);    Wet1    = (float*)p;
    cudaGetSymbolAddress(&p, g_Wet2);    Wet2    = (float*)p;
    cudaGetSymbolAddress(&p, g_smax);    smax    = (unsigned*)p;

    // zero pass-1 state
    cudaMemsetAsync(deg, 0, NN * sizeof(float));
    cudaMemsetAsync(loopsum, 0, (size_t)NN * 16 * sizeof(float));
    cudaMemsetAsync(smax, 0, (size_t)NN * 8 * sizeof(unsigned));
    cudaMemsetAsync(denom, 0, (size_t)NN * 8 * sizeof(float));
    cudaMemsetAsync(agg, 0, (size_t)NN * 1024 * sizeof(float));

    k_deg<<<(EE*16 + 255)/256, 256>>>(ei, ea);
    k_loopattr<<<(NN*16 + 255)/256, 256>>>();
    k_transpose<<<(16*512 + 255)/256, 256>>>(We1, Wet1, 512);
    k_transpose<<<(16*1024 + 255)/256, 256>>>(We2, Wet2, 1024);

    // layer 1 linear transforms
    dim3 g1(512/128, (NN + 127)/128);
    k_sgemm<<<g1, 256>>>(x, Wl1, xl1, NN, 512, FIN);
    k_sgemm<<<g1, 256>>>(x, Wr1, xr1, NN, 512, FIN);

    int nwblk = (EE + NN + 7) / 8;   // 8 warps / 256-thread block
    k_score<512, 64><<<nwblk, 256>>>(ei, ea, xl1, xr1, Wet1, att1);
    k_agg<512, 64><<<nwblk, 256>>>(ei, xl1);
    k_fin1<<<(NN*512 + 255)/256, 256>>>(b1);

    // layer 2 linear transforms
    dim3 g2(1024/128, (NN + 127)/128);
    k_sgemm<<<g2, 256>>>(h1, Wl2, xl2, NN, 1024, 512);
    k_sgemm<<<g2, 256>>>(h1, Wr2, xr2, NN, 1024, 512);

    // reset segment state for layer 2
    cudaMemsetAsync(smax, 0, (size_t)NN * 8 * sizeof(unsigned));
    cudaMemsetAsync(denom, 0, (size_t)NN * 8 * sizeof(float));
    cudaMemsetAsync(agg, 0, (size_t)NN * 1024 * sizeof(float));

    k_score<1024, 128><<<nwblk, 256>>>(ei, ea, xl2, xr2, Wet2, att2);
    k_agg<1024, 128><<<nwblk, 256>>>(ei, xl2);
    k_fin2<<<(NN*128 + 255)/256, 256>>>(b2);

    k_lstm<<<(NN + 7)/8, 256>>>(W_ih, b_ih, b_hh, fcW, fcb, out);
}

// round 2
// speedup vs baseline: 1.2732x; 1.2732x over previous
#include <cuda_runtime.h>
#include <cstdint>

#define NN 50000
#define EE 500000
#define FIN 388

// ---------------- static scratch (no allocation allowed) ----------------
__device__ float    g_xl1[(size_t)NN*512];
__device__ float    g_xr1[(size_t)NN*512];
__device__ float    g_h1 [(size_t)NN*512];
__device__ float    g_xl2[(size_t)NN*1024];
__device__ float    g_xr2[(size_t)NN*1024];
__device__ float    g_agg[(size_t)NN*1024];
__device__ float    g_h2 [(size_t)NN*128];
__device__ float    g_score[(size_t)(EE+NN)*8];
__device__ unsigned g_smax[(size_t)NN*8];
__device__ float    g_denom[(size_t)NN*8];
__device__ float    g_deg[NN];
__device__ float    g_loopsum[(size_t)NN*16];
__device__ float    g_loopattr[(size_t)NN*16];
__device__ float    g_Wet1[512*16];
__device__ float    g_Wet2[1024*16];

// monotonic float <-> uint mapping for atomicMax on floats (any sign)
__device__ __forceinline__ unsigned fkey(float f){
    unsigned u = __float_as_uint(f);
    return (u & 0x80000000u) ? ~u : (u | 0x80000000u);
}
__device__ __forceinline__ float funkey(unsigned u){
    return (u & 0x80000000u) ? __uint_as_float(u & 0x7fffffffu) : __uint_as_float(~u);
}

// ---------------- self-loop attr (mean of incoming edge_attr) ----------------
__global__ void k_deg(const int* __restrict__ ei, const float* __restrict__ ea){
    int t = blockIdx.x * blockDim.x + threadIdx.x;
    if (t >= EE*16) return;
    int e = t >> 4, k = t & 15;
    int dst = ei[EE + e];
    atomicAdd(&g_loopsum[dst*16 + k], ea[t]);
    if (k == 0) atomicAdd(&g_deg[dst], 1.0f);
}

__global__ void k_loopattr(){
    int t = blockIdx.x * blockDim.x + threadIdx.x;
    if (t >= NN*16) return;
    g_loopattr[t] = g_loopsum[t] / fmaxf(g_deg[t >> 4], 1.0f);
}

// transpose We [16, HD] -> Wet [HD, 16] so edge kernels can float4-load it
__global__ void k_transpose(const float* __restrict__ We, float* __restrict__ Wet, int HD){
    int t = blockIdx.x * blockDim.x + threadIdx.x;
    if (t >= 16*HD) return;
    int k = t / HD, j = t % HD;
    Wet[j*16 + k] = We[t];
}

// ---------------- TF32 tensor-core GEMM: C[M,N] = A[M,K] @ B[K,N] ----------------
// 128x128x16 CTA tile, 8 warps (64x32 warp tile), m16n8k8 mma, double-buffered.
__device__ __forceinline__ unsigned cvt_tf32(float f){
    unsigned r;
    asm("cvt.rna.tf32.f32 %0, %1;" : "=r"(r) : "f"(f));
    return r;
}

__device__ __forceinline__ void ldsm4(uint32_t* r, const void* p){
    unsigned addr = (unsigned)__cvta_generic_to_shared(p);
    asm volatile("ldmatrix.sync.aligned.m8n8.x4.shared.b16 {%0,%1,%2,%3}, [%4];"
      : "=r"(r[0]), "=r"(r[1]), "=r"(r[2]), "=r"(r[3]) : "r"(addr));
}

__device__ __forceinline__ void mma_tf32(float* c, const uint32_t* a, const uint32_t* b){
    asm volatile("mma.sync.aligned.m16n8k8.row.col.f32.tf32.tf32.f32 "
        "{%0,%1,%2,%3}, {%4,%5,%6,%7}, {%8,%9}, {%0,%1,%2,%3};"
        : "+f"(c[0]), "+f"(c[1]), "+f"(c[2]), "+f"(c[3])
        : "r"(a[0]), "r"(a[1]), "r"(a[2]), "r"(a[3]), "r"(b[0]), "r"(b[1]));
}

__global__ void __launch_bounds__(256, 2)
k_mma(const float* __restrict__ A, const float* __restrict__ B,
      float* __restrict__ C, int M, int N, int K)
{
    // As: [2][128 rows][20 floats] (pad 20 keeps 16B row alignment, conflict-free ldmatrix)
    // Bs: [2][16 k][128 n] with XOR swizzle of 4-float groups by (k&3)
    __shared__ uint32_t As[2][2560];
    __shared__ uint32_t Bs[2][2048];

    const int tid  = threadIdx.x;
    const int lane = tid & 31, warp = tid >> 5;
    const int wm = (warp & 1) * 64;
    const int wn = (warp >> 1) * 32;
    const int bm = blockIdx.y * 128, bn = blockIdx.x * 128;

    // gmem load mapping
    const int a_m = tid >> 1;              // 0..127
    const int a_k = (tid & 1) * 8;         // 0 or 8 -> two contiguous float4
    const int b_k = tid >> 5;              // 0..7 (and +8 for second float4)
    const int b_n = (tid & 31) * 4;

    // ldmatrix per-lane addressing for A fragments
    const int lrow = ((lane >> 3) & 1) * 8 + (lane & 7);
    const int lkg  = (lane >> 4);          // 0,0,1,1 per 8-lane group
    const int a_frag_base = (wm + lrow) * 20 + lkg * 4;

    float acc[4][4][4];
    #pragma unroll
    for (int i = 0; i < 4; i++)
        #pragma unroll
        for (int j = 0; j < 4; j++)
            #pragma unroll
            for (int q = 0; q < 4; q++) acc[i][j][q] = 0.f;

    const int niter = (K + 15) / 16;

    float4 pa0, pa1, pb0, pb1;
    const float4 z4 = make_float4(0.f, 0.f, 0.f, 0.f);

    // ---- tile load helpers (inlined manually) ----
    int gm = bm + a_m;
    bool arow_ok = (gm < M);
    const float* arow = A + (size_t)gm * K + a_k;

    // prologue: tile 0 -> buf 0
    {
        int k0 = 0;
        pa0 = (arow_ok && k0 + a_k + 4 <= K) ? *(const float4*)(arow + k0) : z4;
        pa1 = (arow_ok && k0 + a_k + 8 <= K) ? *(const float4*)(arow + k0 + 4) : z4;
        pb0 = (k0 + b_k     < K) ? *(const float4*)(B + (size_t)(k0 + b_k    ) * N + bn + b_n) : z4;
        pb1 = (k0 + b_k + 8 < K) ? *(const float4*)(B + (size_t)(k0 + b_k + 8) * N + bn + b_n) : z4;
        uint32_t* da = &As[0][a_m * 20 + a_k];
        da[0]=cvt_tf32(pa0.x); da[1]=cvt_tf32(pa0.y); da[2]=cvt_tf32(pa0.z); da[3]=cvt_tf32(pa0.w);
        da[4]=cvt_tf32(pa1.x); da[5]=cvt_tf32(pa1.y); da[6]=cvt_tf32(pa1.z); da[7]=cvt_tf32(pa1.w);
        unsigned g0 = (((unsigned)(b_n >> 2)) ^ (unsigned)(b_k & 3)) << 2;
        uint32_t* db0 = &Bs[0][b_k * 128 + g0];
        db0[0]=cvt_tf32(pb0.x); db0[1]=cvt_tf32(pb0.y); db0[2]=cvt_tf32(pb0.z); db0[3]=cvt_tf32(pb0.w);
        uint32_t* db1 = &Bs[0][(b_k + 8) * 128 + g0];
        db1[0]=cvt_tf32(pb1.x); db1[1]=cvt_tf32(pb1.y); db1[2]=cvt_tf32(pb1.z); db1[3]=cvt_tf32(pb1.w);
    }
    __syncthreads();

    for (int it = 0; it < niter; it++) {
        int buf = it & 1;
        bool more = (it + 1 < niter);
        if (more) {
            int k0 = (it + 1) * 16;
            pa0 = (arow_ok && k0 + a_k + 4 <= K) ? *(const float4*)(arow + k0) : z4;
            pa1 = (arow_ok && k0 + a_k + 8 <= K) ? *(const float4*)(arow + k0 + 4) : z4;
            pb0 = (k0 + b_k     < K) ? *(const float4*)(B + (size_t)(k0 + b_k    ) * N + bn + b_n) : z4;
            pb1 = (k0 + b_k + 8 < K) ? *(const float4*)(B + (size_t)(k0 + b_k + 8) * N + bn + b_n) : z4;
        }

        #pragma unroll
        for (int s = 0; s < 2; s++) {
            uint32_t af[4][4];
            #pragma unroll
            for (int mt = 0; mt < 4; mt++)
                ldsm4(af[mt], &As[buf][a_frag_base + mt * 320 + s * 8]);

            uint32_t bf[4][2];
            int kk = s * 8 + (lane & 3);
            int nb = (lane >> 2);
            #pragma unroll
            for (int nt = 0; nt < 4; nt++) {
                int n = wn + nt * 8 + nb;
                int idx = (((n >> 2) ^ (lane & 3)) << 2) + (n & 3);
                bf[nt][0] = Bs[buf][kk * 128 + idx];
                bf[nt][1] = Bs[buf][(kk + 4) * 128 + idx];
            }

            #pragma unroll
            for (int mt = 0; mt < 4; mt++)
                #pragma unroll
                for (int nt = 0; nt < 4; nt++)
                    mma_tf32(acc[mt][nt], af[mt], bf[nt]);
        }

        if (more) {
            int nb2 = buf ^ 1;
            uint32_t* da = &As[nb2][a_m * 20 + a_k];
            da[0]=cvt_tf32(pa0.x); da[1]=cvt_tf32(pa0.y); da[2]=cvt_tf32(pa0.z); da[3]=cvt_tf32(pa0.w);
            da[4]=cvt_tf32(pa1.x); da[5]=cvt_tf32(pa1.y); da[6]=cvt_tf32(pa1.z); da[7]=cvt_tf32(pa1.w);
            unsigned g0 = (((unsigned)(b_n >> 2)) ^ (unsigned)(b_k & 3)) << 2;
            uint32_t* db0 = &Bs[nb2][b_k * 128 + g0];
            db0[0]=cvt_tf32(pb0.x); db0[1]=cvt_tf32(pb0.y); db0[2]=cvt_tf32(pb0.z); db0[3]=cvt_tf32(pb0.w);
            uint32_t* db1 = &Bs[nb2][(b_k + 8) * 128 + g0];
            db1[0]=cvt_tf32(pb1.x); db1[1]=cvt_tf32(pb1.y); db1[2]=cvt_tf32(pb1.z); db1[3]=cvt_tf32(pb1.w);
        }
        __syncthreads();
    }

    // epilogue
    #pragma unroll
    for (int mt = 0; mt < 4; mt++) {
        int r0 = bm + wm + mt * 16 + (lane >> 2);
        #pragma unroll
        for (int nt = 0; nt < 4; nt++) {
            int cc = bn + wn + nt * 8 + 2 * (lane & 3);
            if (r0 < M) {
                float2 v = make_float2(acc[mt][nt][0], acc[mt][nt][1]);
                *(float2*)&C[(size_t)r0 * N + cc] = v;
            }
            if (r0 + 8 < M) {
                float2 v = make_float2(acc[mt][nt][2], acc[mt][nt][3]);
                *(float2*)&C[(size_t)(r0 + 8) * N + cc] = v;
            }
        }
    }
}

// ---------------- edge scores: warp per edge (incl. self-loops at E..E+N) ----------------
template<int HD, int D>
__global__ void k_score(const int* __restrict__ ei, const float* __restrict__ eattr,
                        const float* __restrict__ xl, const float* __restrict__ xr,
                        const float* __restrict__ Wet, const float* __restrict__ att)
{
    int gw = (blockIdx.x * blockDim.x + threadIdx.x) >> 5;
    int lane = threadIdx.x & 31;
    if (gw >= EE + NN) return;
    int src, dst; const float* ea;
    if (gw < EE) { src = ei[gw]; dst = ei[EE + gw]; ea = eattr + (size_t)gw * 16; }
    else         { src = gw - EE; dst = src;        ea = g_loopattr + (size_t)src * 16; }

    float4 a0 = ((const float4*)ea)[0];
    float4 a1 = ((const float4*)ea)[1];
    float4 a2 = ((const float4*)ea)[2];
    float4 a3 = ((const float4*)ea)[3];

    const float* xls = xl + (size_t)src * HD;
    const float* xrd = xr + (size_t)dst * HD;
    constexpr int CPH = D / 32;   // c-iterations per head

    float myscore = 0.f;
    #pragma unroll
    for (int h = 0; h < 8; h++) {
        float ph = 0.f;
        #pragma unroll
        for (int cc = 0; cc < CPH; cc++) {
            int c = h * CPH + cc;
            int j = c * 32 + lane;
            const float4* wr = (const float4*)(Wet + (size_t)j * 16);
            float4 w0 = wr[0], w1 = wr[1], w2 = wr[2], w3 = wr[3];
            float ee = a0.x*w0.x + a0.y*w0.y + a0.z*w0.z + a0.w*w0.w
                     + a1.x*w1.x + a1.y*w1.y + a1.z*w1.z + a1.w*w1.w
                     + a2.x*w2.x + a2.y*w2.y + a2.z*w2.z + a2.w*w2.w
                     + a3.x*w3.x + a3.y*w3.y + a3.z*w3.z + a3.w*w3.w;
            float v = xls[j] + xrd[j] + ee;
            v = v > 0.f ? v : 0.2f * v;          // leaky_relu(., 0.2)
            ph += att[j] * v;                     // att[h*D+d] == att[j]
        }
        float s = ph;
        #pragma unroll
        for (int off = 16; off > 0; off >>= 1)
            s += __shfl_xor_sync(0xffffffffu, s, off);
        if (lane == h) myscore = s;
    }
    if (lane < 8) {
        g_score[(size_t)gw * 8 + lane] = myscore;
        atomicMax(&g_smax[dst * 8 + lane], fkey(myscore));
    }
}

// ---------------- fused exp + denom + weighted aggregation ----------------
template<int HD, int D>
__global__ void k_agg(const int* __restrict__ ei, const float* __restrict__ xl)
{
    int gw = (blockIdx.x * blockDim.x + threadIdx.x) >> 5;
    int lane = threadIdx.x & 31;
    if (gw >= EE + NN) return;
    int src, dst;
    if (gw < EE) { src = ei[gw]; dst = ei[EE + gw]; }
    else         { src = gw - EE; dst = src; }

    float w8 = 0.f;
    if (lane < 8) {
        float s = g_score[(size_t)gw * 8 + lane];
        float m = funkey(g_smax[dst * 8 + lane]);
        w8 = __expf(s - m);
        atomicAdd(&g_denom[dst * 8 + lane], w8);
    }
    const float* xls = xl + (size_t)src * HD;
    float* ag = g_agg + (size_t)dst * HD;
    constexpr int CPH = D / 32;
    #pragma unroll
    for (int c = 0; c < HD/32; c++) {
        float w = __shfl_sync(0xffffffffu, w8, c / CPH);
        int j = c * 32 + lane;
        atomicAdd(&ag[j], w * xls[j]);
    }
}

// ---------------- layer finalization ----------------
__global__ void k_fin1(const float* __restrict__ b1){
    int t = blockIdx.x * blockDim.x + threadIdx.x;
    if (t >= NN*512) return;
    int n = t >> 9, j = t & 511, h = j >> 6;
    g_h1[t] = tanhf(g_agg[t] / g_denom[n*8 + h] + b1[j]);
}

__global__ void k_fin2(const float* __restrict__ b2){
    int t = blockIdx.x * blockDim.x + threadIdx.x;
    if (t >= NN*128) return;
    int n = t >> 7, d = t & 127;
    float s = 0.f;
    #pragma unroll
    for (int h = 0; h < 8; h++)
        s += g_agg[(size_t)n*1024 + h*128 + d] / g_denom[n*8 + h];
    g_h2[t] = tanhf(s * 0.125f + b2[d]);
}

// ---------------- single-step LSTM (h0=c0=0) + FC: warp per node ----------------
__global__ void k_lstm(const float* __restrict__ W_ih, const float* __restrict__ b_ih,
                       const float* __restrict__ b_hh, const float* __restrict__ fcW,
                       const float* __restrict__ fcb, float* __restrict__ out)
{
    __shared__ float sh[8][128];
    int w = threadIdx.x >> 5, lane = threadIdx.x & 31;
    int node = blockIdx.x * 8 + w;
    if (node >= NN) return;
    const float* hr = g_h2 + (size_t)node * 128;
    for (int i = lane; i < 128; i += 32) sh[w][i] = hr[i];
    __syncwarp();

    float gates[3];
    const int rows[3] = {lane, 64 + lane, 96 + lane};
    #pragma unroll
    for (int q = 0; q < 3; q++) {
        const float4* wr = (const float4*)(W_ih + (size_t)rows[q] * 128);
        const float4* hv = (const float4*)sh[w];
        float s = 0.f;
        #pragma unroll 8
        for (int k = 0; k < 32; k++) {
            float4 wv = wr[k], xv = hv[k];
            s += wv.x*xv.x + wv.y*xv.y + wv.z*xv.z + wv.w*xv.w;
        }
        gates[q] = s + b_ih[rows[q]] + b_hh[rows[q]];
    }
    float ci = 1.f / (1.f + __expf(-gates[0]));
    float cg = tanhf(gates[1]);
    float co = 1.f / (1.f + __expf(-gates[2]));
    float c  = ci * cg;
    float hid = co * tanhf(c);
    float y = hid * fcW[lane];
    #pragma unroll
    for (int off = 16; off > 0; off >>= 1)
        y += __shfl_xor_sync(0xffffffffu, y, off);
    if (lane == 0) out[node] = y + fcb[0];
}

// ---------------- launch ----------------
extern "C" void kernel_launch(void* const* d_in, const int* in_sizes, int n_in,
                              void* d_out, int out_size)
{
    const float* x    = (const float*)d_in[0];
    const int*   ei   = (const int*)  d_in[1];
    const float* ea   = (const float*)d_in[2];
    const float* Wl1  = (const float*)d_in[3];
    const float* Wr1  = (const float*)d_in[4];
    const float* We1  = (const float*)d_in[5];
    const float* att1 = (const float*)d_in[6];
    const float* b1   = (const float*)d_in[7];
    const float* Wl2  = (const float*)d_in[8];
    const float* Wr2  = (const float*)d_in[9];
    const float* We2  = (const float*)d_in[10];
    const float* att2 = (const float*)d_in[11];
    const float* b2   = (const float*)d_in[12];
    const float* W_ih = (const float*)d_in[13];
    /* d_in[14] = W_hh: unused (h0 = 0) */
    const float* b_ih = (const float*)d_in[15];
    const float* b_hh = (const float*)d_in[16];
    const float* fcW  = (const float*)d_in[17];
    const float* fcb  = (const float*)d_in[18];
    float* out = (float*)d_out;

    void* p;
    float *xl1, *xr1, *xl2, *xr2, *h1, *agg, *denom, *deg, *loopsum, *Wet1, *Wet2;
    unsigned* smax;
    cudaGetSymbolAddress(&p, g_xl1);     xl1     = (float*)p;
    cudaGetSymbolAddress(&p, g_xr1);     xr1     = (float*)p;
    cudaGetSymbolAddress(&p, g_xl2);     xl2     = (float*)p;
    cudaGetSymbolAddress(&p, g_xr2);     xr2     = (float*)p;
    cudaGetSymbolAddress(&p, g_h1);      h1      = (float*)p;
    cudaGetSymbolAddress(&p, g_agg);     agg     = (float*)p;
    cudaGetSymbolAddress(&p, g_denom);   denom   = (float*)p;
    cudaGetSymbolAddress(&p, g_deg);     deg     = (float*)p;
    cudaGetSymbolAddress(&p, g_loopsum); loopsum = (float*)p;
    cudaGetSymbolAddress(&p, g_Wet1);    Wet1    = (float*)p;
    cudaGetSymbolAddress(&p, g_Wet2);    Wet2    = (float*)p;
    cudaGetSymbolAddress(&p, g_smax);    smax    = (unsigned*)p;

    // zero pass-1 state
    cudaMemsetAsync(deg, 0, NN * sizeof(float));
    cudaMemsetAsync(loopsum, 0, (size_t)NN * 16 * sizeof(float));
    cudaMemsetAsync(smax, 0, (size_t)NN * 8 * sizeof(unsigned));
    cudaMemsetAsync(denom, 0, (size_t)NN * 8 * sizeof(float));
    cudaMemsetAsync(agg, 0, (size_t)NN * 1024 * sizeof(float));

    k_deg<<<(EE*16 + 255)/256, 256>>>(ei, ea);
    k_loopattr<<<(NN*16 + 255)/256, 256>>>();
    k_transpose<<<(16*512 + 255)/256, 256>>>(We1, Wet1, 512);
    k_transpose<<<(16*1024 + 255)/256, 256>>>(We2, Wet2, 1024);

    // layer 1 linear transforms (TF32 tensor cores)
    dim3 g1(512/128, (NN + 127)/128);
    k_mma<<<g1, 256>>>(x, Wl1, xl1, NN, 512, FIN);
    k_mma<<<g1, 256>>>(x, Wr1, xr1, NN, 512, FIN);

    int nwblk = (EE + NN + 7) / 8;   // 8 warps / 256-thread block
    k_score<512, 64><<<nwblk, 256>>>(ei, ea, xl1, xr1, Wet1, att1);
    k_agg<512, 64><<<nwblk, 256>>>(ei, xl1);
    k_fin1<<<(NN*512 + 255)/256, 256>>>(b1);

    // layer 2 linear transforms
    dim3 g2(1024/128, (NN + 127)/128);
    k_mma<<<g2, 256>>>(h1, Wl2, xl2, NN, 1024, 512);
    k_mma<<<g2, 256>>>(h1, Wr2, xr2, NN, 1024, 512);

    // reset segment state for layer 2
    cudaMemsetAsync(smax, 0, (size_t)NN * 8 * sizeof(unsigned));
    cudaMemsetAsync(denom, 0, (size_t)NN * 8 * sizeof(float));
    cudaMemsetAsync(agg, 0, (size_t)NN * 1024 * sizeof(float));

    k_score<1024, 128><<<nwblk, 256>>>(ei, ea, xl2, xr2, Wet2, att2);
    k_agg<1024, 128><<<nwblk, 256>>>(ei, xl2);
    k_fin2<<<(NN*128 + 255)/256, 256>>>(b2);

    k_lstm<<<(NN + 7)/8, 256>>>(W_ih, b_ih, b_hh, fcW, fcb, out);
}

// round 3
// speedup vs baseline: 1.3635x; 1.0709x over previous
#include <cuda_runtime.h>
#include <cuda_bf16.h>
#include <cstdint>

#define NN 50000
#define EE 500000
#define FIN 388
#define KP1 400    // FIN padded to multiple of 16

typedef __nv_bfloat16 bf16;

// ---------------- static scratch (no allocation allowed) ----------------
__device__ __align__(16) bf16 g_xh  [(size_t)NN*KP1];
__device__ __align__(16) bf16 g_Wl1h[KP1*512];
__device__ __align__(16) bf16 g_Wr1h[KP1*512];
__device__ __align__(16) bf16 g_xl1 [(size_t)NN*512];
__device__ __align__(16) bf16 g_xr1 [(size_t)NN*512];
__device__ __align__(16) bf16 g_h1h [(size_t)NN*512];
__device__ __align__(16) bf16 g_Wl2h[512*1024];
__device__ __align__(16) bf16 g_Wr2h[512*1024];
__device__ __align__(16) bf16 g_xl2 [(size_t)NN*1024];
__device__ __align__(16) bf16 g_xr2 [(size_t)NN*1024];

__device__ float    g_agg[(size_t)NN*1024];
__device__ float    g_h2 [(size_t)NN*128];
__device__ float    g_score[(size_t)(EE+NN)*8];
__device__ unsigned g_smax[(size_t)NN*8];
__device__ float    g_denom[(size_t)NN*8];
__device__ float    g_deg[NN];
__device__ float    g_loopsum[(size_t)NN*16];
__device__ float    g_loopattr[(size_t)NN*16];
__device__ float    g_Wet1[512*16];
__device__ float    g_Wet2[1024*16];

// monotonic float <-> uint mapping for atomicMax on floats (any sign)
__device__ __forceinline__ unsigned fkey(float f){
    unsigned u = __float_as_uint(f);
    return (u & 0x80000000u) ? ~u : (u | 0x80000000u);
}
__device__ __forceinline__ float funkey(unsigned u){
    return (u & 0x80000000u) ? __uint_as_float(u & 0x7fffffffu) : __uint_as_float(~u);
}

// ---------------- fused zero of all per-call state ----------------
__global__ void k_zero(){
    size_t t = (size_t)blockIdx.x * blockDim.x + threadIdx.x;
    if (t < (size_t)NN*1024) g_agg[t] = 0.f;
    if (t < (size_t)NN*8) { g_smax[t] = 0u; g_denom[t] = 0.f; }
    if (t < (size_t)NN*16) g_loopsum[t] = 0.f;
    if (t < NN) g_deg[t] = 0.f;
}

// ---------------- conversions to bf16 ----------------
// pad columns: in [n][ci] fp32 -> out [n][co] bf16 (zeros beyond ci)
__global__ void k_padcols(const float* __restrict__ in, bf16* __restrict__ out,
                          int ci, int co, long n){
    long t = (long)blockIdx.x * blockDim.x + threadIdx.x;
    if (t >= n * co) return;
    long r = t / co; int c = (int)(t - r * co);
    out[t] = (c < ci) ? __float2bfloat16_rn(in[r * ci + c]) : __float2bfloat16_rn(0.f);
}
// pad rows: in [ri][cols] fp32 -> out [ro][cols] bf16
__global__ void k_padrows(const float* __restrict__ in, bf16* __restrict__ out,
                          int ri, int ro, int cols){
    int t = blockIdx.x * blockDim.x + threadIdx.x;
    if (t >= ro * cols) return;
    int r = t / cols;
    out[t] = (r < ri) ? __float2bfloat16_rn(in[t]) : __float2bfloat16_rn(0.f);
}

// ---------------- self-loop attr (mean of incoming edge_attr) ----------------
__global__ void k_deg(const int* __restrict__ ei, const float* __restrict__ ea){
    int t = blockIdx.x * blockDim.x + threadIdx.x;
    if (t >= EE*16) return;
    int e = t >> 4, k = t & 15;
    int dst = ei[EE + e];
    atomicAdd(&g_loopsum[dst*16 + k], ea[t]);
    if (k == 0) atomicAdd(&g_deg[dst], 1.0f);
}

__global__ void k_loopattr(){
    int t = blockIdx.x * blockDim.x + threadIdx.x;
    if (t >= NN*16) return;
    g_loopattr[t] = g_loopsum[t] / fmaxf(g_deg[t >> 4], 1.0f);
}

// transpose We [16, HD] -> Wet [HD, 16]
__global__ void k_transpose(const float* __restrict__ We, float* __restrict__ Wet, int HD){
    int t = blockIdx.x * blockDim.x + threadIdx.x;
    if (t >= 16*HD) return;
    int k = t / HD, j = t % HD;
    Wet[j*16 + k] = We[t];
}

// ---------------- bf16 tensor-core GEMM: C[M,N] = A[M,K] @ B[K,N] ----------------
// 128x128x16 tile, 8 warps (64x32 warp tile), m16n8k16 bf16 mma, double-buffered.
__device__ __forceinline__ void ldsm4(uint32_t* r, const void* p){
    unsigned a = (unsigned)__cvta_generic_to_shared(p);
    asm volatile("ldmatrix.sync.aligned.m8n8.x4.shared.b16 {%0,%1,%2,%3}, [%4];"
      : "=r"(r[0]), "=r"(r[1]), "=r"(r[2]), "=r"(r[3]) : "r"(a));
}
__device__ __forceinline__ void ldsm4t(uint32_t* r, const void* p){
    unsigned a = (unsigned)__cvta_generic_to_shared(p);
    asm volatile("ldmatrix.sync.aligned.m8n8.x4.trans.shared.b16 {%0,%1,%2,%3}, [%4];"
      : "=r"(r[0]), "=r"(r[1]), "=r"(r[2]), "=r"(r[3]) : "r"(a));
}
__device__ __forceinline__ void mma_bf16(float* c, const uint32_t* a, const uint32_t* b){
    asm volatile("mma.sync.aligned.m16n8k16.row.col.f32.bf16.bf16.f32 "
        "{%0,%1,%2,%3}, {%4,%5,%6,%7}, {%8,%9}, {%0,%1,%2,%3};"
        : "+f"(c[0]), "+f"(c[1]), "+f"(c[2]), "+f"(c[3])
        : "r"(a[0]), "r"(a[1]), "r"(a[2]), "r"(a[3]), "r"(b[0]), "r"(b[1]));
}

__global__ void __launch_bounds__(256, 2)
k_hgemm(const bf16* __restrict__ A, const bf16* __restrict__ B, bf16* __restrict__ C,
        int M, int N, int K)   // K % 16 == 0, N % 128 == 0
{
    __shared__ __align__(16) bf16 As[2][128*40];   // rows padded 32 -> 40 halves
    __shared__ __align__(16) bf16 Bs[2][16*128];   // [k][n], groups XOR-swizzled by k&7

    const int tid  = threadIdx.x;
    const int lane = tid & 31, warp = tid >> 5;
    const int wm = (warp & 1) * 64;
    const int wn = (warp >> 1) * 32;
    const int bm = blockIdx.y * 128, bn = blockIdx.x * 128;

    // gmem->smem mapping (one uint4 = 8 halves per buffer per thread)
    const int ar = tid >> 1, aseg = (tid & 1) * 8;
    const int bk = tid >> 4, bg = tid & 15;
    const int gm = bm + ar;
    const bool aok = (gm < M);
    const bf16* aptr = A + (size_t)gm * K + aseg;
    const int bsw = ((bg ^ (bk & 7)) * 8);

    // fragment addressing
    const int a_off = (wm + (lane & 15)) * 40 + (lane >> 4) * 8;
    const int b_kk  = lane & 15;
    const int b_ng0 = (wn >> 3) + (lane >> 4);   // + p*2 per n-pair

    float acc[4][4][4];
    #pragma unroll
    for (int i=0;i<4;i++) for (int j=0;j<4;j++) for (int q=0;q<4;q++) acc[i][j][q]=0.f;

    const int niter = K / 16;
    const uint4 z4 = make_uint4(0,0,0,0);
    uint4 pa, pb;

    // prologue: tile 0 -> buf 0
    pa = aok ? *(const uint4*)(aptr) : z4;
    pb = *(const uint4*)(B + (size_t)bk * N + bn + bg * 8);
    *(uint4*)&As[0][ar * 40 + aseg] = pa;
    *(uint4*)&Bs[0][bk * 128 + bsw] = pb;
    __syncthreads();

    for (int it = 0; it < niter; it++) {
        int buf = it & 1;
        bool more = (it + 1 < niter);
        if (more) {
            int k0 = (it + 1) * 16;
            pa = aok ? *(const uint4*)(aptr + k0) : z4;
            pb = *(const uint4*)(B + (size_t)(k0 + bk) * N + bn + bg * 8);
        }

        uint32_t af[4][4];
        #pragma unroll
        for (int mt = 0; mt < 4; mt++)
            ldsm4(af[mt], &As[buf][a_off + mt * 16 * 40]);

        uint32_t bfr[2][4];
        #pragma unroll
        for (int p = 0; p < 2; p++) {
            int sg = ((b_ng0 + p * 2) ^ (b_kk & 7));
            ldsm4t(bfr[p], &Bs[buf][b_kk * 128 + sg * 8]);
        }

        #pragma unroll
        for (int mt = 0; mt < 4; mt++)
            #pragma unroll
            for (int p = 0; p < 2; p++) {
                mma_bf16(acc[mt][p*2+0], af[mt], &bfr[p][0]);
                mma_bf16(acc[mt][p*2+1], af[mt], &bfr[p][2]);
            }

        if (more) {
            int nb = buf ^ 1;
            *(uint4*)&As[nb][ar * 40 + aseg] = pa;
            *(uint4*)&Bs[nb][bk * 128 + bsw] = pb;
        }
        __syncthreads();
    }

    // epilogue: write bf16
    #pragma unroll
    for (int mt = 0; mt < 4; mt++) {
        int r0 = bm + wm + mt * 16 + (lane >> 2);
        #pragma unroll
        for (int nt = 0; nt < 4; nt++) {
            int cc = bn + wn + nt * 8 + 2 * (lane & 3);
            if (r0 < M)
                *(__nv_bfloat162*)&C[(size_t)r0 * N + cc] =
                    __floats2bfloat162_rn(acc[mt][nt][0], acc[mt][nt][1]);
            if (r0 + 8 < M)
                *(__nv_bfloat162*)&C[(size_t)(r0 + 8) * N + cc] =
                    __floats2bfloat162_rn(acc[mt][nt][2], acc[mt][nt][3]);
        }
    }
}

// ---------------- edge scores: warp per edge (incl. self-loops at E..E+N) ----------------
template<int HD, int D>
__global__ void k_score(const int* __restrict__ ei, const float* __restrict__ eattr,
                        const bf16* __restrict__ xl, const bf16* __restrict__ xr,
                        const float* __restrict__ Wet, const float* __restrict__ att)
{
    int gw = (blockIdx.x * blockDim.x + threadIdx.x) >> 5;
    int lane = threadIdx.x & 31;
    if (gw >= EE + NN) return;
    int src, dst; const float* ea;
    if (gw < EE) { src = ei[gw]; dst = ei[EE + gw]; ea = eattr + (size_t)gw * 16; }
    else         { src = gw - EE; dst = src;        ea = g_loopattr + (size_t)src * 16; }

    float4 a0 = ((const float4*)ea)[0];
    float4 a1 = ((const float4*)ea)[1];
    float4 a2 = ((const float4*)ea)[2];
    float4 a3 = ((const float4*)ea)[3];

    const bf16* xls = xl + (size_t)src * HD;
    const bf16* xrd = xr + (size_t)dst * HD;
    constexpr int CPH = D / 32;

    float myscore = 0.f;
    #pragma unroll
    for (int h = 0; h < 8; h++) {
        float ph = 0.f;
        #pragma unroll
        for (int cc = 0; cc < CPH; cc++) {
            int c = h * CPH + cc;
            int j = c * 32 + lane;
            const float4* wr = (const float4*)(Wet + (size_t)j * 16);
            float4 w0 = wr[0], w1 = wr[1], w2 = wr[2], w3 = wr[3];
            float ee = a0.x*w0.x + a0.y*w0.y + a0.z*w0.z + a0.w*w0.w
                     + a1.x*w1.x + a1.y*w1.y + a1.z*w1.z + a1.w*w1.w
                     + a2.x*w2.x + a2.y*w2.y + a2.z*w2.z + a2.w*w2.w
                     + a3.x*w3.x + a3.y*w3.y + a3.z*w3.z + a3.w*w3.w;
            float v = __bfloat162float(xls[j]) + __bfloat162float(xrd[j]) + ee;
            v = v > 0.f ? v : 0.2f * v;
            ph += att[j] * v;
        }
        float s = ph;
        #pragma unroll
        for (int off = 16; off > 0; off >>= 1)
            s += __shfl_xor_sync(0xffffffffu, s, off);
        if (lane == h) myscore = s;
    }
    if (lane < 8) {
        g_score[(size_t)gw * 8 + lane] = myscore;
        atomicMax(&g_smax[dst * 8 + lane], fkey(myscore));
    }
}

// ---------------- fused exp + denom + weighted aggregation ----------------
template<int HD, int D>
__global__ void k_agg(const int* __restrict__ ei, const bf16* __restrict__ xl)
{
    int gw = (blockIdx.x * blockDim.x + threadIdx.x) >> 5;
    int lane = threadIdx.x & 31;
    if (gw >= EE + NN) return;
    int src, dst;
    if (gw < EE) { src = ei[gw]; dst = ei[EE + gw]; }
    else         { src = gw - EE; dst = src; }

    float w8 = 0.f;
    if (lane < 8) {
        float s = g_score[(size_t)gw * 8 + lane];
        float m = funkey(g_smax[dst * 8 + lane]);
        w8 = __expf(s - m);
        atomicAdd(&g_denom[dst * 8 + lane], w8);
    }
    const bf16* xls = xl + (size_t)src * HD;
    float* ag = g_agg + (size_t)dst * HD;
    constexpr int CPH = D / 32;
    #pragma unroll
    for (int c = 0; c < HD/32; c++) {
        float w = __shfl_sync(0xffffffffu, w8, c / CPH);
        int j = c * 32 + lane;
        atomicAdd(&ag[j], w * __bfloat162float(xls[j]));
    }
}

// ---------------- layer finalization ----------------
__global__ void k_fin1(const float* __restrict__ b1){
    int t = blockIdx.x * blockDim.x + threadIdx.x;
    if (t >= NN*512) return;
    int n = t >> 9, j = t & 511, h = j >> 6;
    g_h1h[t] = __float2bfloat16_rn(tanhf(g_agg[t] / g_denom[n*8 + h] + b1[j]));
}

__global__ void k_fin2(const float* __restrict__ b2){
    int t = blockIdx.x * blockDim.x + threadIdx.x;
    if (t >= NN*128) return;
    int n = t >> 7, d = t & 127;
    float s = 0.f;
    #pragma unroll
    for (int h = 0; h < 8; h++)
        s += g_agg[(size_t)n*1024 + h*128 + d] / g_denom[n*8 + h];
    g_h2[t] = tanhf(s * 0.125f + b2[d]);
}

// ---------------- single-step LSTM (h0=c0=0) + FC: warp per node ----------------
__global__ void k_lstm(const float* __restrict__ W_ih, const float* __restrict__ b_ih,
                       const float* __restrict__ b_hh, const float* __restrict__ fcW,
                       const float* __restrict__ fcb, float* __restrict__ out)
{
    __shared__ float sh[8][128];
    int w = threadIdx.x >> 5, lane = threadIdx.x & 31;
    int node = blockIdx.x * 8 + w;
    if (node >= NN) return;
    const float* hr = g_h2 + (size_t)node * 128;
    for (int i = lane; i < 128; i += 32) sh[w][i] = hr[i];
    __syncwarp();

    float gates[3];
    const int rows[3] = {lane, 64 + lane, 96 + lane};
    #pragma unroll
    for (int q = 0; q < 3; q++) {
        const float4* wr = (const float4*)(W_ih + (size_t)rows[q] * 128);
        const float4* hv = (const float4*)sh[w];
        float s = 0.f;
        #pragma unroll 8
        for (int k = 0; k < 32; k++) {
            float4 wv = wr[k], xv = hv[k];
            s += wv.x*xv.x + wv.y*xv.y + wv.z*xv.z + wv.w*xv.w;
        }
        gates[q] = s + b_ih[rows[q]] + b_hh[rows[q]];
    }
    float ci = 1.f / (1.f + __expf(-gates[0]));
    float cg = tanhf(gates[1]);
    float co = 1.f / (1.f + __expf(-gates[2]));
    float c  = ci * cg;
    float hid = co * tanhf(c);
    float y = hid * fcW[lane];
    #pragma unroll
    for (int off = 16; off > 0; off >>= 1)
        y += __shfl_xor_sync(0xffffffffu, y, off);
    if (lane == 0) out[node] = y + fcb[0];
}

// ---------------- launch ----------------
extern "C" void kernel_launch(void* const* d_in, const int* in_sizes, int n_in,
                              void* d_out, int out_size)
{
    const float* x    = (const float*)d_in[0];
    const int*   ei   = (const int*)  d_in[1];
    const float* ea   = (const float*)d_in[2];
    const float* Wl1  = (const float*)d_in[3];
    const float* Wr1  = (const float*)d_in[4];
    const float* We1  = (const float*)d_in[5];
    const float* att1 = (const float*)d_in[6];
    const float* b1   = (const float*)d_in[7];
    const float* Wl2  = (const float*)d_in[8];
    const float* Wr2  = (const float*)d_in[9];
    const float* We2  = (const float*)d_in[10];
    const float* att2 = (const float*)d_in[11];
    const float* b2   = (const float*)d_in[12];
    const float* W_ih = (const float*)d_in[13];
    /* d_in[14] = W_hh: unused (h0 = 0) */
    const float* b_ih = (const float*)d_in[15];
    const float* b_hh = (const float*)d_in[16];
    const float* fcW  = (const float*)d_in[17];
    const float* fcb  = (const float*)d_in[18];
    float* out = (float*)d_out;

    void* p;
    bf16 *xh, *Wl1h, *Wr1h, *xl1, *xr1, *h1h, *Wl2h, *Wr2h, *xl2, *xr2;
    float *agg, *denom, *Wet1, *Wet2;
    unsigned* smax;
    cudaGetSymbolAddress(&p, g_xh);    xh   = (bf16*)p;
    cudaGetSymbolAddress(&p, g_Wl1h);  Wl1h = (bf16*)p;
    cudaGetSymbolAddress(&p, g_Wr1h);  Wr1h = (bf16*)p;
    cudaGetSymbolAddress(&p, g_xl1);   xl1  = (bf16*)p;
    cudaGetSymbolAddress(&p, g_xr1);   xr1  = (bf16*)p;
    cudaGetSymbolAddress(&p, g_h1h);   h1h  = (bf16*)p;
    cudaGetSymbolAddress(&p, g_Wl2h);  Wl2h = (bf16*)p;
    cudaGetSymbolAddress(&p, g_Wr2h);  Wr2h = (bf16*)p;
    cudaGetSymbolAddress(&p, g_xl2);   xl2  = (bf16*)p;
    cudaGetSymbolAddress(&p, g_xr2);   xr2  = (bf16*)p;
    cudaGetSymbolAddress(&p, g_agg);   agg  = (float*)p;
    cudaGetSymbolAddress(&p, g_denom); denom= (float*)p;
    cudaGetSymbolAddress(&p, g_Wet1);  Wet1 = (float*)p;
    cudaGetSymbolAddress(&p, g_Wet2);  Wet2 = (float*)p;
    cudaGetSymbolAddress(&p, g_smax);  smax = (unsigned*)p;

    // 1: zero all per-call state (one kernel instead of 5 memsets)
    k_zero<<<(int)(((size_t)NN*1024 + 255)/256), 256>>>();
    // 2-4: bf16 conversions needed for layer-1 GEMMs
    k_padcols<<<(int)(((long)NN*KP1 + 255)/256), 256>>>(x, xh, FIN, KP1, NN);
    k_padrows<<<(KP1*512 + 255)/256, 256>>>(Wl1, Wl1h, FIN, KP1, 512);
    k_padrows<<<(KP1*512 + 255)/256, 256>>>(Wr1, Wr1h, FIN, KP1, 512);
    // 5
    k_deg<<<(EE*16 + 255)/256, 256>>>(ei, ea);
    // 6-7: layer-1 GEMMs (bf16 tensor cores)
    dim3 g1(512/128, (NN + 127)/128);
    k_hgemm<<<g1, 256>>>(xh, Wl1h, xl1, NN, 512, KP1);
    k_hgemm<<<g1, 256>>>(xh, Wr1h, xr1, NN, 512, KP1);
    // remaining prep
    k_padrows<<<(512*1024 + 255)/256, 256>>>(Wl2, Wl2h, 512, 512, 1024);
    k_padrows<<<(512*1024 + 255)/256, 256>>>(Wr2, Wr2h, 512, 512, 1024);
    k_loopattr<<<(NN*16 + 255)/256, 256>>>();
    k_transpose<<<(16*512 + 255)/256, 256>>>(We1, Wet1, 512);
    k_transpose<<<(16*1024 + 255)/256, 256>>>(We2, Wet2, 1024);

    int nwblk = (EE + NN + 7) / 8;
    k_score<512, 64><<<nwblk, 256>>>(ei, ea, xl1, xr1, Wet1, att1);
    k_agg<512, 64><<<nwblk, 256>>>(ei, xl1);
    k_fin1<<<(NN*512 + 255)/256, 256>>>(b1);

    dim3 g2(1024/128, (NN + 127)/128);
    k_hgemm<<<g2, 256>>>(h1h, Wl2h, xl2, NN, 1024, 512);
    k_hgemm<<<g2, 256>>>(h1h, Wr2h, xr2, NN, 1024, 512);

    cudaMemsetAsync(smax, 0, (size_t)NN * 8 * sizeof(unsigned));
    cudaMemsetAsync(denom, 0, (size_t)NN * 8 * sizeof(float));
    cudaMemsetAsync(agg, 0, (size_t)NN * 1024 * sizeof(float));

    k_score<1024, 128><<<nwblk, 256>>>(ei, ea, xl2, xr2, Wet2, att2);
    k_agg<1024, 128><<<nwblk, 256>>>(ei, xl2);
    k_fin2<<<(NN*128 + 255)/256, 256>>>(b2);

    k_lstm<<<(NN + 7)/8, 256>>>(W_ih, b_ih, b_hh, fcW, fcb, out);
}

// round 4
// speedup vs baseline: 3.8428x; 2.8184x over previous
#include <cuda_runtime.h>
#include <cuda_bf16.h>
#include <cstdint>

#define NN 50000
#define EE 500000
#define FIN 388
#define KP1 400    // FIN padded to multiple of 16

typedef __nv_bfloat16 bf16;

// ---------------- static scratch (no allocation allowed) ----------------
__device__ __align__(16) bf16 g_xh  [(size_t)NN*KP1];
__device__ __align__(16) bf16 g_Wl1h[KP1*512];
__device__ __align__(16) bf16 g_Wr1h[KP1*512];
__device__ __align__(16) bf16 g_We1h[16*512];
__device__ __align__(16) bf16 g_xl1 [(size_t)NN*512];
__device__ __align__(16) bf16 g_xr1 [(size_t)NN*512];
__device__ __align__(16) bf16 g_h1h [(size_t)NN*512];
__device__ __align__(16) bf16 g_Wl2h[512*1024];
__device__ __align__(16) bf16 g_Wr2h[512*1024];
__device__ __align__(16) bf16 g_We2h[16*1024];
__device__ __align__(16) bf16 g_xl2 [(size_t)NN*1024];
__device__ __align__(16) bf16 g_xr2 [(size_t)NN*1024];
__device__ __align__(16) bf16 g_eah [(size_t)(EE+NN)*16];
__device__ __align__(16) bf16 g_ee1 [(size_t)(EE+NN)*512];
__device__ __align__(16) bf16 g_ee2 [(size_t)(EE+NN)*1024];

__device__ float g_h2 [(size_t)NN*128];
__device__ float g_loopsum[(size_t)NN*16];
__device__ float g_loopattr[(size_t)NN*16];
__device__ int   g_cnt[NN];
__device__ int   g_offs[NN+1];
__device__ int   g_cursor[NN];
__device__ int   g_csrsrc[EE];
__device__ int   g_csreid[EE];

// ---------------- small init ----------------
__global__ void k_zero0(){
    int t = blockIdx.x * blockDim.x + threadIdx.x;
    if (t < NN*16) g_loopsum[t] = 0.f;
    if (t < NN) g_cnt[t] = 0;
}

// ---------------- conversions to bf16 ----------------
__global__ void k_padcols(const float* __restrict__ in, bf16* __restrict__ out,
                          int ci, int co, long n){
    long t = (long)blockIdx.x * blockDim.x + threadIdx.x;
    if (t >= n * co) return;
    long r = t / co; int c = (int)(t - r * co);
    out[t] = (c < ci) ? __float2bfloat16_rn(in[r * ci + c]) : __float2bfloat16_rn(0.f);
}
__global__ void k_padrows(const float* __restrict__ in, bf16* __restrict__ out,
                          int ri, int ro, int cols){
    int t = blockIdx.x * blockDim.x + threadIdx.x;
    if (t >= ro * cols) return;
    int r = t / cols;
    out[t] = (r < ri) ? __float2bfloat16_rn(in[t]) : __float2bfloat16_rn(0.f);
}

// ---------------- degree + loop-attr sums + int counts ----------------
__global__ void k_deg(const int* __restrict__ ei, const float* __restrict__ ea){
    int t = blockIdx.x * blockDim.x + threadIdx.x;
    if (t >= EE*16) return;
    int e = t >> 4, k = t & 15;
    int dst = ei[EE + e];
    atomicAdd(&g_loopsum[dst*16 + k], ea[t]);
    if (k == 0) atomicAdd(&g_cnt[dst], 1);
}

__global__ void k_loopattr(){
    int t = blockIdx.x * blockDim.x + threadIdx.x;
    if (t >= NN*16) return;
    g_loopattr[t] = g_loopsum[t] / fmaxf((float)g_cnt[t >> 4], 1.0f);
}

// exclusive scan of g_cnt -> g_offs / g_cursor (single block, 1024 threads)
__global__ void k_scan(){
    const int C = (NN + 1023) / 1024;
    int t = threadIdx.x, lane = t & 31, w = t >> 5;
    int s = 0;
    for (int i = 0; i < C; i++){ int idx = t*C + i; if (idx < NN) s += g_cnt[idx]; }
    int v = s;
    #pragma unroll
    for (int o = 1; o < 32; o <<= 1){ int u = __shfl_up_sync(~0u, v, o); if (lane >= o) v += u; }
    __shared__ int ws[32];
    if (lane == 31) ws[w] = v;
    __syncthreads();
    if (w == 0){
        int u2 = ws[lane];
        #pragma unroll
        for (int o = 1; o < 32; o <<= 1){ int u = __shfl_up_sync(~0u, u2, o); if (lane >= o) u2 += u; }
        ws[lane] = u2;
    }
    __syncthreads();
    int pref = v - s + (w > 0 ? ws[w-1] : 0);
    for (int i = 0; i < C; i++){
        int idx = t*C + i;
        if (idx < NN){ g_offs[idx] = pref; g_cursor[idx] = pref; pref += g_cnt[idx]; }
    }
    if (t == 1023) g_offs[NN] = pref;
}

__global__ void k_scatter(const int* __restrict__ ei){
    int e = blockIdx.x * blockDim.x + threadIdx.x;
    if (e >= EE) return;
    int s = ei[e], d = ei[EE + e];
    int pos = atomicAdd(&g_cursor[d], 1);
    g_csrsrc[pos] = s;
    g_csreid[pos] = e;
}

// build bf16 edge-attr matrix [(EE+NN)][16] (rows EE.. are self-loop attrs)
__global__ void k_eah(const float* __restrict__ ea){
    long t = (long)blockIdx.x * blockDim.x + threadIdx.x;
    if (t >= (long)(EE+NN)*16) return;
    long e = t >> 4; int k = (int)(t & 15);
    float v = (e < EE) ? ea[t] : g_loopattr[(e - EE)*16 + k];
    ((bf16*)g_eah)[t] = __float2bfloat16_rn(v);
}

// ---------------- bf16 tensor-core GEMM (unchanged from round 3) ----------------
__device__ __forceinline__ void ldsm4(uint32_t* r, const void* p){
    unsigned a = (unsigned)__cvta_generic_to_shared(p);
    asm volatile("ldmatrix.sync.aligned.m8n8.x4.shared.b16 {%0,%1,%2,%3}, [%4];"
      : "=r"(r[0]), "=r"(r[1]), "=r"(r[2]), "=r"(r[3]) : "r"(a));
}
__device__ __forceinline__ void ldsm4t(uint32_t* r, const void* p){
    unsigned a = (unsigned)__cvta_generic_to_shared(p);
    asm volatile("ldmatrix.sync.aligned.m8n8.x4.trans.shared.b16 {%0,%1,%2,%3}, [%4];"
      : "=r"(r[0]), "=r"(r[1]), "=r"(r[2]), "=r"(r[3]) : "r"(a));
}
__device__ __forceinline__ void mma_bf16(float* c, const uint32_t* a, const uint32_t* b){
    asm volatile("mma.sync.aligned.m16n8k16.row.col.f32.bf16.bf16.f32 "
        "{%0,%1,%2,%3}, {%4,%5,%6,%7}, {%8,%9}, {%0,%1,%2,%3};"
        : "+f"(c[0]), "+f"(c[1]), "+f"(c[2]), "+f"(c[3])
        : "r"(a[0]), "r"(a[1]), "r"(a[2]), "r"(a[3]), "r"(b[0]), "r"(b[1]));
}

__global__ void __launch_bounds__(256, 2)
k_hgemm(const bf16* __restrict__ A, const bf16* __restrict__ B, bf16* __restrict__ C,
        int M, int N, int K)   // K % 16 == 0, N % 128 == 0
{
    __shared__ __align__(16) bf16 As[2][128*40];
    __shared__ __align__(16) bf16 Bs[2][16*128];

    const int tid  = threadIdx.x;
    const int lane = tid & 31, warp = tid >> 5;
    const int wm = (warp & 1) * 64;
    const int wn = (warp >> 1) * 32;
    const int bm = blockIdx.y * 128, bn = blockIdx.x * 128;

    const int ar = tid >> 1, aseg = (tid & 1) * 8;
    const int bk = tid >> 4, bg = tid & 15;
    const int gm = bm + ar;
    const bool aok = (gm < M);
    const bf16* aptr = A + (size_t)gm * K + aseg;
    const int bsw = ((bg ^ (bk & 7)) * 8);

    const int a_off = (wm + (lane & 15)) * 40 + (lane >> 4) * 8;
    const int b_kk  = lane & 15;
    const int b_ng0 = (wn >> 3) + (lane >> 4);

    float acc[4][4][4];
    #pragma unroll
    for (int i=0;i<4;i++) for (int j=0;j<4;j++) for (int q=0;q<4;q++) acc[i][j][q]=0.f;

    const int niter = K / 16;
    const uint4 z4 = make_uint4(0,0,0,0);
    uint4 pa, pb;

    pa = aok ? *(const uint4*)(aptr) : z4;
    pb = *(const uint4*)(B + (size_t)bk * N + bn + bg * 8);
    *(uint4*)&As[0][ar * 40 + aseg] = pa;
    *(uint4*)&Bs[0][bk * 128 + bsw] = pb;
    __syncthreads();

    for (int it = 0; it < niter; it++) {
        int buf = it & 1;
        bool more = (it + 1 < niter);
        if (more) {
            int k0 = (it + 1) * 16;
            pa = aok ? *(const uint4*)(aptr + k0) : z4;
            pb = *(const uint4*)(B + (size_t)(k0 + bk) * N + bn + bg * 8);
        }

        uint32_t af[4][4];
        #pragma unroll
        for (int mt = 0; mt < 4; mt++)
            ldsm4(af[mt], &As[buf][a_off + mt * 16 * 40]);

        uint32_t bfr[2][4];
        #pragma unroll
        for (int p = 0; p < 2; p++) {
            int sg = ((b_ng0 + p * 2) ^ (b_kk & 7));
            ldsm4t(bfr[p], &Bs[buf][b_kk * 128 + sg * 8]);
        }

        #pragma unroll
        for (int mt = 0; mt < 4; mt++)
            #pragma unroll
            for (int p = 0; p < 2; p++) {
                mma_bf16(acc[mt][p*2+0], af[mt], &bfr[p][0]);
                mma_bf16(acc[mt][p*2+1], af[mt], &bfr[p][2]);
            }

        if (more) {
            int nb = buf ^ 1;
            *(uint4*)&As[nb][ar * 40 + aseg] = pa;
            *(uint4*)&Bs[nb][bk * 128 + bsw] = pb;
        }
        __syncthreads();
    }

    #pragma unroll
    for (int mt = 0; mt < 4; mt++) {
        int r0 = bm + wm + mt * 16 + (lane >> 2);
        #pragma unroll
        for (int nt = 0; nt < 4; nt++) {
            int cc = bn + wn + nt * 8 + 2 * (lane & 3);
            if (r0 < M)
                *(__nv_bfloat162*)&C[(size_t)r0 * N + cc] =
                    __floats2bfloat162_rn(acc[mt][nt][0], acc[mt][nt][1]);
            if (r0 + 8 < M)
                *(__nv_bfloat162*)&C[(size_t)(r0 + 8) * N + cc] =
                    __floats2bfloat162_rn(acc[mt][nt][2], acc[mt][nt][3]);
        }
    }
}

// ---------------- fused node-centric GAT layer ----------------
// CTA (128 thr) per node: scores over CSR in-edges + self-loop, softmax, aggregate.
// Feature pairs: thread t, slice f handles j = 2*(t + 128*f) and j+1.
// head(w, f) = (64*w + 256*f) / D  is uniform within a warp.
template<int HD, int D, bool CONCAT>
__global__ void __launch_bounds__(128)
k_node(const bf16* __restrict__ xl, const bf16* __restrict__ xr,
       const bf16* __restrict__ ee, const float* __restrict__ att,
       const float* __restrict__ bias, bf16* __restrict__ out_b,
       float* __restrict__ out_f)
{
    constexpr int F = HD / 256;
    constexpr int SMAX = 96;
    const int n = blockIdx.x;
    const int t = threadIdx.x, w = t >> 5, lane = t & 31;

    __shared__ float2 xr_s[HD/2];
    __shared__ float  scw[SMAX][4][F];
    __shared__ float  a_s[SMAX*8];
    __shared__ int    srcs[SMAX];
    __shared__ int    eids[SMAX];
    __shared__ float2 red[128];

    const int e0 = g_offs[n];
    int deg = g_offs[n+1] - e0; if (deg > SMAX-1) deg = SMAX-1;
    const int ne = deg + 1;

    int hf[F];
    float2 av[F];
    #pragma unroll
    for (int f = 0; f < F; f++){
        int j2 = t + 128*f;
        __nv_bfloat162 v = ((const __nv_bfloat162*)(xr + (size_t)n*HD))[j2];
        xr_s[j2] = make_float2(__low2float(v), __high2float(v));
        av[f] = *(const float2*)&att[2*j2];
        hf[f] = (64*w + 256*f) / D;
    }
    if (t < ne){
        if (t < deg){ srcs[t] = g_csrsrc[e0 + t]; eids[t] = g_csreid[e0 + t]; }
        else        { srcs[t] = n; eids[t] = EE + n; }
    }
    __syncthreads();

    // phase A: per-edge attention scores (per-warp partials, no intra-loop syncs)
    for (int e = 0; e < ne; e++){
        const __nv_bfloat162* xl2 = (const __nv_bfloat162*)(xl + (size_t)srcs[e]*HD);
        const __nv_bfloat162* ee2 = (const __nv_bfloat162*)(ee + (size_t)eids[e]*HD);
        #pragma unroll
        for (int f = 0; f < F; f++){
            int j2 = t + 128*f;
            __nv_bfloat162 xv = xl2[j2];
            __nv_bfloat162 ev = ee2[j2];
            float2 xs = xr_s[j2];
            float vx = __low2float(xv)  + xs.x + __low2float(ev);
            float vy = __high2float(xv) + xs.y + __high2float(ev);
            vx = vx > 0.f ? vx : 0.2f*vx;
            vy = vy > 0.f ? vy : 0.2f*vy;
            float p = av[f].x*vx + av[f].y*vy;
            #pragma unroll
            for (int o = 16; o > 0; o >>= 1) p += __shfl_xor_sync(~0u, p, o);
            if (lane == 0) scw[e][w][f] = p;
        }
    }
    __syncthreads();

    // softmax per head (threads 0..7)
    if (t < 8){
        float m = -1e30f;
        for (int e = 0; e < ne; e++){
            float s = 0.f;
            #pragma unroll
            for (int w2 = 0; w2 < 4; w2++)
                #pragma unroll
                for (int f = 0; f < F; f++)
                    if ((64*w2 + 256*f) / D == t) s += scw[e][w2][f];
            a_s[e*8 + t] = s;
            m = fmaxf(m, s);
        }
        float den = 0.f;
        for (int e = 0; e < ne; e++){
            float x = __expf(a_s[e*8 + t] - m);
            a_s[e*8 + t] = x; den += x;
        }
        float inv = 1.f / den;
        for (int e = 0; e < ne; e++) a_s[e*8 + t] *= inv;
    }
    __syncthreads();

    // phase B: weighted aggregation (xl re-gather hits L2)
    float2 acc[F];
    #pragma unroll
    for (int f = 0; f < F; f++) acc[f] = make_float2(0.f, 0.f);
    for (int e = 0; e < ne; e++){
        const __nv_bfloat162* xl2 = (const __nv_bfloat162*)(xl + (size_t)srcs[e]*HD);
        #pragma unroll
        for (int f = 0; f < F; f++){
            float a = a_s[e*8 + hf[f]];
            __nv_bfloat162 xv = xl2[t + 128*f];
            acc[f].x += a * __low2float(xv);
            acc[f].y += a * __high2float(xv);
        }
    }

    if (CONCAT){
        #pragma unroll
        for (int f = 0; f < F; f++){
            int j = 2*(t + 128*f);
            float ox = tanhf(acc[f].x + bias[j]);
            float oy = tanhf(acc[f].y + bias[j+1]);
            ((__nv_bfloat162*)(out_b + (size_t)n*HD))[t + 128*f] = __floats2bfloat162_rn(ox, oy);
        }
    } else {
        float2 loc = make_float2(0.f, 0.f);
        #pragma unroll
        for (int f = 0; f < F; f++){ loc.x += acc[f].x; loc.y += acc[f].y; }
        red[t] = loc;
        __syncthreads();
        if (t < 64){
            float2 tot = make_float2(red[t].x + red[t+64].x, red[t].y + red[t+64].y);
            int d = 2*t;
            out_f[(size_t)n*128 + d]     = tanhf(tot.x * 0.125f + bias[d]);
            out_f[(size_t)n*128 + d + 1] = tanhf(tot.y * 0.125f + bias[d+1]);
        }
    }
}

// ---------------- single-step LSTM (h0=c0=0) + FC: warp per node ----------------
__global__ void k_lstm(const float* __restrict__ W_ih, const float* __restrict__ b_ih,
                       const float* __restrict__ b_hh, const float* __restrict__ fcW,
                       const float* __restrict__ fcb, float* __restrict__ out)
{
    __shared__ float sh[8][128];
    int w = threadIdx.x >> 5, lane = threadIdx.x & 31;
    int node = blockIdx.x * 8 + w;
    if (node >= NN) return;
    const float* hr = g_h2 + (size_t)node * 128;
    for (int i = lane; i < 128; i += 32) sh[w][i] = hr[i];
    __syncwarp();

    float gates[3];
    const int rows[3] = {lane, 64 + lane, 96 + lane};
    #pragma unroll
    for (int q = 0; q < 3; q++) {
        const float4* wr = (const float4*)(W_ih + (size_t)rows[q] * 128);
        const float4* hv = (const float4*)sh[w];
        float s = 0.f;
        #pragma unroll 8
        for (int k = 0; k < 32; k++) {
            float4 wv = wr[k], xv = hv[k];
            s += wv.x*xv.x + wv.y*xv.y + wv.z*xv.z + wv.w*xv.w;
        }
        gates[q] = s + b_ih[rows[q]] + b_hh[rows[q]];
    }
    float ci = 1.f / (1.f + __expf(-gates[0]));
    float cg = tanhf(gates[1]);
    float co = 1.f / (1.f + __expf(-gates[2]));
    float c  = ci * cg;
    float hid = co * tanhf(c);
    float y = hid * fcW[lane];
    #pragma unroll
    for (int off = 16; off > 0; off >>= 1)
        y += __shfl_xor_sync(0xffffffffu, y, off);
    if (lane == 0) out[node] = y + fcb[0];
}

// ---------------- launch ----------------
extern "C" void kernel_launch(void* const* d_in, const int* in_sizes, int n_in,
                              void* d_out, int out_size)
{
    const float* x    = (const float*)d_in[0];
    const int*   ei   = (const int*)  d_in[1];
    const float* ea   = (const float*)d_in[2];
    const float* Wl1  = (const float*)d_in[3];
    const float* Wr1  = (const float*)d_in[4];
    const float* We1  = (const float*)d_in[5];
    const float* att1 = (const float*)d_in[6];
    const float* b1   = (const float*)d_in[7];
    const float* Wl2  = (const float*)d_in[8];
    const float* Wr2  = (const float*)d_in[9];
    const float* We2  = (const float*)d_in[10];
    const float* att2 = (const float*)d_in[11];
    const float* b2   = (const float*)d_in[12];
    const float* W_ih = (const float*)d_in[13];
    /* d_in[14] = W_hh: unused (h0 = 0) */
    const float* b_ih = (const float*)d_in[15];
    const float* b_hh = (const float*)d_in[16];
    const float* fcW  = (const float*)d_in[17];
    const float* fcb  = (const float*)d_in[18];
    float* out = (float*)d_out;

    void* p;
    bf16 *xh, *Wl1h, *Wr1h, *We1h, *xl1, *xr1, *h1h, *Wl2h, *Wr2h, *We2h, *xl2, *xr2;
    bf16 *eah, *ee1, *ee2;
    cudaGetSymbolAddress(&p, g_xh);    xh   = (bf16*)p;
    cudaGetSymbolAddress(&p, g_Wl1h);  Wl1h = (bf16*)p;
    cudaGetSymbolAddress(&p, g_Wr1h);  Wr1h = (bf16*)p;
    cudaGetSymbolAddress(&p, g_We1h);  We1h = (bf16*)p;
    cudaGetSymbolAddress(&p, g_xl1);   xl1  = (bf16*)p;
    cudaGetSymbolAddress(&p, g_xr1);   xr1  = (bf16*)p;
    cudaGetSymbolAddress(&p, g_h1h);   h1h  = (bf16*)p;
    cudaGetSymbolAddress(&p, g_Wl2h);  Wl2h = (bf16*)p;
    cudaGetSymbolAddress(&p, g_Wr2h);  Wr2h = (bf16*)p;
    cudaGetSymbolAddress(&p, g_We2h);  We2h = (bf16*)p;
    cudaGetSymbolAddress(&p, g_xl2);   xl2  = (bf16*)p;
    cudaGetSymbolAddress(&p, g_xr2);   xr2  = (bf16*)p;
    cudaGetSymbolAddress(&p, g_eah);   eah  = (bf16*)p;
    cudaGetSymbolAddress(&p, g_ee1);   ee1  = (bf16*)p;
    cudaGetSymbolAddress(&p, g_ee2);   ee2  = (bf16*)p;
    float* h2; cudaGetSymbolAddress(&p, g_h2); h2 = (float*)p;

    // 1: tiny zero (counts + loopsum)
    k_zero0<<<(NN*16 + 255)/256, 256>>>();
    // 2-4: conversions for layer-1 node GEMMs
    k_padcols<<<(int)(((long)NN*KP1 + 255)/256), 256>>>(x, xh, FIN, KP1, NN);
    k_padrows<<<(KP1*512 + 255)/256, 256>>>(Wl1, Wl1h, FIN, KP1, 512);
    k_padrows<<<(KP1*512 + 255)/256, 256>>>(Wr1, Wr1h, FIN, KP1, 512);
    // 5-6: layer-1 node GEMMs (6th launch = profiled one)
    dim3 g1(512/128, (NN + 127)/128);
    k_hgemm<<<g1, 256>>>(xh, Wl1h, xl1, NN, 512, KP1);
    k_hgemm<<<g1, 256>>>(xh, Wr1h, xr1, NN, 512, KP1);
    // CSR + self-loop attrs
    k_deg<<<(EE*16 + 255)/256, 256>>>(ei, ea);
    k_scan<<<1, 1024>>>();
    k_loopattr<<<(NN*16 + 255)/256, 256>>>();
    k_scatter<<<(EE + 255)/256, 256>>>(ei);
    k_eah<<<(int)(((long)(EE+NN)*16 + 255)/256), 256>>>(ea);
    // ee1 = eah @ We1
    k_padrows<<<(16*512 + 255)/256, 256>>>(We1, We1h, 16, 16, 512);
    dim3 ge1(512/128, (EE + NN + 127)/128);
    k_hgemm<<<ge1, 256>>>(eah, We1h, ee1, EE + NN, 512, 16);
    // fused GAT layer 1
    k_node<512, 64, true><<<NN, 128>>>(xl1, xr1, ee1, att1, b1, h1h, nullptr);

    // layer 2
    k_padrows<<<(512*1024 + 255)/256, 256>>>(Wl2, Wl2h, 512, 512, 1024);
    k_padrows<<<(512*1024 + 255)/256, 256>>>(Wr2, Wr2h, 512, 512, 1024);
    k_padrows<<<(16*1024 + 255)/256, 256>>>(We2, We2h, 16, 16, 1024);
    dim3 g2(1024/128, (NN + 127)/128);
    k_hgemm<<<g2, 256>>>(h1h, Wl2h, xl2, NN, 1024, 512);
    k_hgemm<<<g2, 256>>>(h1h, Wr2h, xr2, NN, 1024, 512);
    dim3 ge2(1024/128, (EE + NN + 127)/128);
    k_hgemm<<<ge2, 256>>>(eah, We2h, ee2, EE + NN, 1024, 16);
    k_node<1024, 128, false><<<NN, 128>>>(xl2, xr2, ee2, att2, b2, nullptr, h2);

    k_lstm<<<(NN + 7)/8, 256>>>(W_ih, b_ih, b_hh, fcW, fcb, out);
}

// round 6
// speedup vs baseline: 4.2469x; 1.1052x over previous
#include <cuda_runtime.h>
#include <cuda_bf16.h>
#include <cstdint>

#define NN 50000
#define EE 500000
#define FIN 388
#define KP1 400    // FIN padded to multiple of 16

typedef __nv_bfloat16 bf16;

// ---------------- static scratch (no allocation allowed) ----------------
__device__ __align__(16) bf16 g_xh  [(size_t)NN*KP1];
__device__ __align__(16) bf16 g_Wl1h[KP1*512];
__device__ __align__(16) bf16 g_Wr1h[KP1*512];
__device__ __align__(16) bf16 g_We1h[16*512];
__device__ __align__(16) bf16 g_xl1 [(size_t)NN*512];
__device__ __align__(16) bf16 g_xr1 [(size_t)NN*512];
__device__ __align__(16) bf16 g_h1h [(size_t)NN*512];
__device__ __align__(16) bf16 g_Wl2h[512*1024];
__device__ __align__(16) bf16 g_Wr2h[512*1024];
__device__ __align__(16) bf16 g_We2h[16*1024];
__device__ __align__(16) bf16 g_xl2 [(size_t)NN*1024];
__device__ __align__(16) bf16 g_xr2 [(size_t)NN*1024];
__device__ __align__(16) bf16 g_eah [(size_t)(EE+NN)*16];
__device__ __align__(16) bf16 g_ee1 [(size_t)(EE+NN)*512];
__device__ __align__(16) bf16 g_ee2 [(size_t)(EE+NN)*1024];

__device__ float g_h2 [(size_t)NN*128];
__device__ float g_loopattr[(size_t)NN*16];
__device__ int   g_cnt[NN];
__device__ int   g_offs[NN+1];
__device__ int   g_cursor[NN];
__device__ int   g_csrsrc[EE];
__device__ int   g_csreid[EE];

// ---------------- conversions to bf16 ----------------
__global__ void k_padcols(const float* __restrict__ in, bf16* __restrict__ out,
                          int ci, int co, long n){
    long t = (long)blockIdx.x * blockDim.x + threadIdx.x;
    if (t >= n * co) return;
    long r = t / co; int c = (int)(t - r * co);
    out[t] = (c < ci) ? __float2bfloat16_rn(in[r * ci + c]) : __float2bfloat16_rn(0.f);
}
__global__ void k_padrows(const float* __restrict__ in, bf16* __restrict__ out,
                          int ri, int ro, int cols){
    int t = blockIdx.x * blockDim.x + threadIdx.x;
    if (t >= ro * cols) return;
    int r = t / cols;
    out[t] = (r < ri) ? __float2bfloat16_rn(in[t]) : __float2bfloat16_rn(0.f);
}

// ---------------- CSR construction ----------------
__global__ void k_cnt(const int* __restrict__ ei){
    int e = blockIdx.x * blockDim.x + threadIdx.x;
    if (e < EE) atomicAdd(&g_cnt[ei[EE + e]], 1);
}

// exclusive scan of g_cnt -> g_offs / g_cursor (single block, 1024 threads)
__global__ void k_scan(){
    const int C = (NN + 1023) / 1024;
    int t = threadIdx.x, lane = t & 31, w = t >> 5;
    int s = 0;
    for (int i = 0; i < C; i++){ int idx = t*C + i; if (idx < NN) s += g_cnt[idx]; }
    int v = s;
    #pragma unroll
    for (int o = 1; o < 32; o <<= 1){ int u = __shfl_up_sync(~0u, v, o); if (lane >= o) v += u; }
    __shared__ int ws[32];
    if (lane == 31) ws[w] = v;
    __syncthreads();
    if (w == 0){
        int u2 = ws[lane];
        #pragma unroll
        for (int o = 1; o < 32; o <<= 1){ int u = __shfl_up_sync(~0u, u2, o); if (lane >= o) u2 += u; }
        ws[lane] = u2;
    }
    __syncthreads();
    int pref = v - s + (w > 0 ? ws[w-1] : 0);
    for (int i = 0; i < C; i++){
        int idx = t*C + i;
        if (idx < NN){ g_offs[idx] = pref; g_cursor[idx] = pref; pref += g_cnt[idx]; }
    }
    if (t == 1023) g_offs[NN] = pref;
}

__global__ void k_scatter(const int* __restrict__ ei){
    int e = blockIdx.x * blockDim.x + threadIdx.x;
    if (e >= EE) return;
    int s = ei[e], d = ei[EE + e];
    int pos = atomicAdd(&g_cursor[d], 1);
    g_csrsrc[pos] = s;
    g_csreid[pos] = e;
}

// loop_attr = mean of incoming edge_attr, gathered over CSR (no atomics)
__global__ void k_loopattr(const float* __restrict__ ea){
    int n = blockIdx.x * 8 + (threadIdx.x >> 5);
    if (n >= NN) return;
    int l = threadIdx.x & 31, ep = l >> 4, k = l & 15;
    int e0 = g_offs[n], deg = g_offs[n+1] - e0;
    float s = 0.f;
    for (int e = ep; e < deg; e += 2)
        s += ea[(size_t)g_csreid[e0 + e]*16 + k];
    s += __shfl_xor_sync(~0u, s, 16);
    if (l < 16) g_loopattr[n*16 + l] = s / fmaxf((float)deg, 1.f);
}

// build bf16 edge-attr matrix [(EE+NN)][16] (rows EE.. are self-loop attrs)
__global__ void k_eah(const float* __restrict__ ea){
    long t = (long)blockIdx.x * blockDim.x + threadIdx.x;
    if (t >= (long)(EE+NN)*16) return;
    long e = t >> 4; int k = (int)(t & 15);
    float v = (e < EE) ? ea[t] : g_loopattr[(e - EE)*16 + k];
    g_eah[t] = __float2bfloat16_rn(v);
}

// ---------------- bf16 tensor-core GEMM ----------------
__device__ __forceinline__ void ldsm4(uint32_t* r, const void* p){
    unsigned a = (unsigned)__cvta_generic_to_shared(p);
    asm volatile("ldmatrix.sync.aligned.m8n8.x4.shared.b16 {%0,%1,%2,%3}, [%4];"
      : "=r"(r[0]), "=r"(r[1]), "=r"(r[2]), "=r"(r[3]) : "r"(a));
}
__device__ __forceinline__ void ldsm4t(uint32_t* r, const void* p){
    unsigned a = (unsigned)__cvta_generic_to_shared(p);
    asm volatile("ldmatrix.sync.aligned.m8n8.x4.trans.shared.b16 {%0,%1,%2,%3}, [%4];"
      : "=r"(r[0]), "=r"(r[1]), "=r"(r[2]), "=r"(r[3]) : "r"(a));
}
__device__ __forceinline__ void mma_bf16(float* c, const uint32_t* a, const uint32_t* b){
    asm volatile("mma.sync.aligned.m16n8k16.row.col.f32.bf16.bf16.f32 "
        "{%0,%1,%2,%3}, {%4,%5,%6,%7}, {%8,%9}, {%0,%1,%2,%3};"
        : "+f"(c[0]), "+f"(c[1]), "+f"(c[2]), "+f"(c[3])
        : "r"(a[0]), "r"(a[1]), "r"(a[2]), "r"(a[3]), "r"(b[0]), "r"(b[1]));
}

__global__ void __launch_bounds__(256, 2)
k_hgemm(const bf16* __restrict__ A, const bf16* __restrict__ B, bf16* __restrict__ C,
        int M, int N, int K)   // K % 16 == 0, N % 128 == 0
{
    __shared__ __align__(16) bf16 As[2][128*40];
    __shared__ __align__(16) bf16 Bs[2][16*128];

    const int tid  = threadIdx.x;
    const int lane = tid & 31, warp = tid >> 5;
    const int wm = (warp & 1) * 64;
    const int wn = (warp >> 1) * 32;
    const int bm = blockIdx.y * 128, bn = blockIdx.x * 128;

    const int ar = tid >> 1, aseg = (tid & 1) * 8;
    const int bk = tid >> 4, bg = tid & 15;
    const int gm = bm + ar;
    const bool aok = (gm < M);
    const bf16* aptr = A + (size_t)gm * K + aseg;
    const int bsw = ((bg ^ (bk & 7)) * 8);

    const int a_off = (wm + (lane & 15)) * 40 + (lane >> 4) * 8;
    const int b_kk  = lane & 15;
    const int b_ng0 = (wn >> 3) + (lane >> 4);

    float acc[4][4][4];
    #pragma unroll
    for (int i=0;i<4;i++) for (int j=0;j<4;j++) for (int q=0;q<4;q++) acc[i][j][q]=0.f;

    const int niter = K / 16;
    const uint4 z4 = make_uint4(0,0,0,0);
    uint4 pa, pb;

    pa = aok ? *(const uint4*)(aptr) : z4;
    pb = *(const uint4*)(B + (size_t)bk * N + bn + bg * 8);
    *(uint4*)&As[0][ar * 40 + aseg] = pa;
    *(uint4*)&Bs[0][bk * 128 + bsw] = pb;
    __syncthreads();

    for (int it = 0; it < niter; it++) {
        int buf = it & 1;
        bool more = (it + 1 < niter);
        if (more) {
            int k0 = (it + 1) * 16;
            pa = aok ? *(const uint4*)(aptr + k0) : z4;
            pb = *(const uint4*)(B + (size_t)(k0 + bk) * N + bn + bg * 8);
        }

        uint32_t af[4][4];
        #pragma unroll
        for (int mt = 0; mt < 4; mt++)
            ldsm4(af[mt], &As[buf][a_off + mt * 16 * 40]);

        uint32_t bfr[2][4];
        #pragma unroll
        for (int p = 0; p < 2; p++) {
            int sg = ((b_ng0 + p * 2) ^ (b_kk & 7));
            ldsm4t(bfr[p], &Bs[buf][b_kk * 128 + sg * 8]);
        }

        #pragma unroll
        for (int mt = 0; mt < 4; mt++)
            #pragma unroll
            for (int p = 0; p < 2; p++) {
                mma_bf16(acc[mt][p*2+0], af[mt], &bfr[p][0]);
                mma_bf16(acc[mt][p*2+1], af[mt], &bfr[p][2]);
            }

        if (more) {
            int nb = buf ^ 1;
            *(uint4*)&As[nb][ar * 40 + aseg] = pa;
            *(uint4*)&Bs[nb][bk * 128 + bsw] = pb;
        }
        __syncthreads();
    }

    #pragma unroll
    for (int mt = 0; mt < 4; mt++) {
        int r0 = bm + wm + mt * 16 + (lane >> 2);
        #pragma unroll
        for (int nt = 0; nt < 4; nt++) {
            int cc = bn + wn + nt * 8 + 2 * (lane & 3);
            if (r0 < M)
                *(__nv_bfloat162*)&C[(size_t)r0 * N + cc] =
                    __floats2bfloat162_rn(acc[mt][nt][0], acc[mt][nt][1]);
            if (r0 + 8 < M)
                *(__nv_bfloat162*)&C[(size_t)(r0 + 8) * N + cc] =
                    __floats2bfloat162_rn(acc[mt][nt][2], acc[mt][nt][3]);
        }
    }
}

// ---------------- fused node-centric GAT layer, online softmax ----------------
// 128 threads per node. Head-aligned mapping: group g of warp w covers one head
// slice; thread handles 4 features j = (HD/4)*w + 128*g + 4*l (one uint2 load).
// Scores reduce within REDW lanes (16 for D=64, 32 for D=128) -> per-group
// online softmax state (m, den, acc[4]) with rescale-on-new-max. Single pass.
template<int HD, int NG, int REDW, bool CONCAT>
__global__ void __launch_bounds__(128)
k_node(const bf16* __restrict__ xl, const bf16* __restrict__ xr,
       const bf16* __restrict__ ee, const float* __restrict__ att,
       const float* __restrict__ bias, bf16* __restrict__ out_b,
       float* __restrict__ out_f)
{
    const int n = blockIdx.x;
    const int t = threadIdx.x, w = t >> 5, l = t & 31;

    // uint2 (= 2 x bf162 = 4 features) index per group
    int q[NG];
    #pragma unroll
    for (int g = 0; g < NG; g++) q[g] = (HD/16)*w + 32*g + l;

    // thread-private xr and att (head-aligned => no sharing needed)
    float xr4[NG][4], at4[NG][4];
    {
        const uint2* xr2 = (const uint2*)(xr + (size_t)n * HD);
        #pragma unroll
        for (int g = 0; g < NG; g++){
            uint2 xv = xr2[q[g]];
            __nv_bfloat162 p0 = *(__nv_bfloat162*)&xv.x;
            __nv_bfloat162 p1 = *(__nv_bfloat162*)&xv.y;
            xr4[g][0] = __low2float(p0); xr4[g][1] = __high2float(p0);
            xr4[g][2] = __low2float(p1); xr4[g][3] = __high2float(p1);
            float4 a = *(const float4*)&att[4*q[g]];
            at4[g][0] = a.x; at4[g][1] = a.y; at4[g][2] = a.z; at4[g][3] = a.w;
        }
    }

    float m[NG], den[NG], acc[NG][4];
    #pragma unroll
    for (int g = 0; g < NG; g++){
        m[g] = -1e30f; den[g] = 0.f;
        acc[g][0]=acc[g][1]=acc[g][2]=acc[g][3]=0.f;
    }

    const int e0 = g_offs[n];
    const int deg = g_offs[n+1] - e0;

    for (int e = 0; e <= deg; e++){
        int src, eid;
        if (e < deg){ src = g_csrsrc[e0 + e]; eid = g_csreid[e0 + e]; }
        else        { src = n; eid = EE + n; }
        const uint2* xl2 = (const uint2*)(xl + (size_t)src * HD);
        const uint2* ee2 = (const uint2*)(ee + (size_t)eid * HD);
        #pragma unroll
        for (int g = 0; g < NG; g++){
            uint2 xv = xl2[q[g]];
            uint2 ev = ee2[q[g]];
            __nv_bfloat162 x0 = *(__nv_bfloat162*)&xv.x;
            __nv_bfloat162 x1 = *(__nv_bfloat162*)&xv.y;
            __nv_bfloat162 e0v = *(__nv_bfloat162*)&ev.x;
            __nv_bfloat162 e1v = *(__nv_bfloat162*)&ev.y;
            float xf[4] = {__low2float(x0), __high2float(x0),
                           __low2float(x1), __high2float(x1)};
            float ef[4] = {__low2float(e0v), __high2float(e0v),
                           __low2float(e1v), __high2float(e1v)};
            float p = 0.f;
            #pragma unroll
            for (int i = 0; i < 4; i++){
                float v = xf[i] + xr4[g][i] + ef[i];
                v = v > 0.f ? v : 0.2f * v;
                p += at4[g][i] * v;
            }
            #pragma unroll
            for (int o = REDW/2; o > 0; o >>= 1)
                p += __shfl_xor_sync(~0u, p, o);
            // online softmax update (p == score s, warp-group-uniform)
            float mn = fmaxf(m[g], p);
            float sc = __expf(m[g] - mn);
            float pv = __expf(p - mn);
            m[g] = mn;
            den[g] = den[g] * sc + pv;
            #pragma unroll
            for (int i = 0; i < 4; i++)
                acc[g][i] = acc[g][i] * sc + pv * xf[i];
        }
    }

    if (CONCAT){
        __nv_bfloat162* ob = (__nv_bfloat162*)(out_b + (size_t)n * HD);
        #pragma unroll
        for (int g = 0; g < NG; g++){
            float inv = 1.f / den[g];
            int j = 4*q[g];
            float4 b = *(const float4*)&bias[j];
            float o0 = tanhf(acc[g][0]*inv + b.x);
            float o1 = tanhf(acc[g][1]*inv + b.y);
            float o2 = tanhf(acc[g][2]*inv + b.z);
            float o3 = tanhf(acc[g][3]*inv + b.w);
            ob[2*q[g]]     = __floats2bfloat162_rn(o0, o1);
            ob[2*q[g] + 1] = __floats2bfloat162_rn(o2, o3);
        }
    } else {
        // mean over 8 heads: head = 2w+g holds d = 4l..4l+3
        __shared__ float sm[8][128];
        #pragma unroll
        for (int g = 0; g < NG; g++){
            float inv = 1.f / den[g];
            int head = 2*w + g;
            #pragma unroll
            for (int i = 0; i < 4; i++)
                sm[head][4*l + i] = acc[g][i] * inv;
        }
        __syncthreads();
        float s = 0.f;
        #pragma unroll
        for (int h = 0; h < 8; h++) s += sm[h][t];
        out_f[(size_t)n*128 + t] = tanhf(s * 0.125f + bias[t]);
    }
}

// ---------------- single-step LSTM (h0=c0=0) + FC: warp per node ----------------
__global__ void k_lstm(const float* __restrict__ W_ih, const float* __restrict__ b_ih,
                       const float* __restrict__ b_hh, const float* __restrict__ fcW,
                       const float* __restrict__ fcb, float* __restrict__ out)
{
    __shared__ float sh[8][128];
    int w = threadIdx.x >> 5, lane = threadIdx.x & 31;
    int node = blockIdx.x * 8 + w;
    if (node >= NN) return;
    const float* hr = g_h2 + (size_t)node * 128;
    for (int i = lane; i < 128; i += 32) sh[w][i] = hr[i];
    __syncwarp();

    float gates[3];
    const int rows[3] = {lane, 64 + lane, 96 + lane};
    #pragma unroll
    for (int q = 0; q < 3; q++) {
        const float4* wr = (const float4*)(W_ih + (size_t)rows[q] * 128);
        const float4* hv = (const float4*)sh[w];
        float s = 0.f;
        #pragma unroll 8
        for (int k = 0; k < 32; k++) {
            float4 wv = wr[k], xv = hv[k];
            s += wv.x*xv.x + wv.y*xv.y + wv.z*xv.z + wv.w*xv.w;
        }
        gates[q] = s + b_ih[rows[q]] + b_hh[rows[q]];
    }
    float ci = 1.f / (1.f + __expf(-gates[0]));
    float cg = tanhf(gates[1]);
    float co = 1.f / (1.f + __expf(-gates[2]));
    float c  = ci * cg;
    float hid = co * tanhf(c);
    float y = hid * fcW[lane];
    #pragma unroll
    for (int off = 16; off > 0; off >>= 1)
        y += __shfl_xor_sync(0xffffffffu, y, off);
    if (lane == 0) out[node] = y + fcb[0];
}

// ---------------- launch ----------------
extern "C" void kernel_launch(void* const* d_in, const int* in_sizes, int n_in,
                              void* d_out, int out_size)
{
    const float* x    = (const float*)d_in[0];
    const int*   ei   = (const int*)  d_in[1];
    const float* ea   = (const float*)d_in[2];
    const float* Wl1  = (const float*)d_in[3];
    const float* Wr1  = (const float*)d_in[4];
    const float* We1  = (const float*)d_in[5];
    const float* att1 = (const float*)d_in[6];
    const float* b1   = (const float*)d_in[7];
    const float* Wl2  = (const float*)d_in[8];
    const float* Wr2  = (const float*)d_in[9];
    const float* We2  = (const float*)d_in[10];
    const float* att2 = (const float*)d_in[11];
    const float* b2   = (const float*)d_in[12];
    const float* W_ih = (const float*)d_in[13];
    /* d_in[14] = W_hh: unused (h0 = 0) */
    const float* b_ih = (const float*)d_in[15];
    const float* b_hh = (const float*)d_in[16];
    const float* fcW  = (const float*)d_in[17];
    const float* fcb  = (const float*)d_in[18];
    float* out = (float*)d_out;

    void* p;
    bf16 *xh, *Wl1h, *Wr1h, *We1h, *xl1, *xr1, *h1h, *Wl2h, *Wr2h, *We2h, *xl2, *xr2;
    bf16 *eah, *ee1, *ee2;
    int* cnt;
    cudaGetSymbolAddress(&p, g_xh);    xh   = (bf16*)p;
    cudaGetSymbolAddress(&p, g_Wl1h);  Wl1h = (bf16*)p;
    cudaGetSymbolAddress(&p, g_Wr1h);  Wr1h = (bf16*)p;
    cudaGetSymbolAddress(&p, g_We1h);  We1h = (bf16*)p;
    cudaGetSymbolAddress(&p, g_xl1);   xl1  = (bf16*)p;
    cudaGetSymbolAddress(&p, g_xr1);   xr1  = (bf16*)p;
    cudaGetSymbolAddress(&p, g_h1h);   h1h  = (bf16*)p;
    cudaGetSymbolAddress(&p, g_Wl2h);  Wl2h = (bf16*)p;
    cudaGetSymbolAddress(&p, g_Wr2h);  Wr2h = (bf16*)p;
    cudaGetSymbolAddress(&p, g_We2h);  We2h = (bf16*)p;
    cudaGetSymbolAddress(&p, g_xl2);   xl2  = (bf16*)p;
    cudaGetSymbolAddress(&p, g_xr2);   xr2  = (bf16*)p;
    cudaGetSymbolAddress(&p, g_eah);   eah  = (bf16*)p;
    cudaGetSymbolAddress(&p, g_ee1);   ee1  = (bf16*)p;
    cudaGetSymbolAddress(&p, g_ee2);   ee2  = (bf16*)p;
    cudaGetSymbolAddress(&p, g_cnt);   cnt  = (int*)p;
    float* h2; cudaGetSymbolAddress(&p, g_h2); h2 = (float*)p;

    cudaMemsetAsync(cnt, 0, NN * sizeof(int));

    // bf16 conversions for layer-1 GEMMs
    k_padcols<<<(int)(((long)NN*KP1 + 255)/256), 256>>>(x, xh, FIN, KP1, NN);
    k_padrows<<<(KP1*512 + 255)/256, 256>>>(Wl1, Wl1h, FIN, KP1, 512);
    k_padrows<<<(KP1*512 + 255)/256, 256>>>(Wr1, Wr1h, FIN, KP1, 512);
    // CSR counts
    k_cnt<<<(EE + 255)/256, 256>>>(ei);
    // layer-1 node GEMMs
    dim3 g1(512/128, (NN + 127)/128);
    k_hgemm<<<g1, 256>>>(xh, Wl1h, xl1, NN, 512, KP1);
    k_hgemm<<<g1, 256>>>(xh, Wr1h, xr1, NN, 512, KP1);
    // CSR finish + self-loop attrs (gathered, no float atomics)
    k_scan<<<1, 1024>>>();
    k_scatter<<<(EE + 255)/256, 256>>>(ei);
    k_loopattr<<<(NN + 7)/8, 256>>>(ea);
    k_eah<<<(int)(((long)(EE+NN)*16 + 255)/256), 256>>>(ea);
    // ee1 = eah @ We1
    k_padrows<<<(16*512 + 255)/256, 256>>>(We1, We1h, 16, 16, 512);
    dim3 ge1(512/128, (EE + NN + 127)/128);
    k_hgemm<<<ge1, 256>>>(eah, We1h, ee1, EE + NN, 512, 16);
    // fused GAT layer 1 (online softmax)
    k_node<512, 1, 16, true><<<NN, 128>>>(xl1, xr1, ee1, att1, b1, h1h, nullptr);

    // layer 2
    k_padrows<<<(512*1024 + 255)/256, 256>>>(Wl2, Wl2h, 512, 512, 1024);
    k_padrows<<<(512*1024 + 255)/256, 256>>>(Wr2, Wr2h, 512, 512, 1024);
    k_padrows<<<(16*1024 + 255)/256, 256>>>(We2, We2h, 16, 16, 1024);
    dim3 g2(1024/128, (NN + 127)/128);
    k_hgemm<<<g2, 256>>>(h1h, Wl2h, xl2, NN, 1024, 512);
    k_hgemm<<<g2, 256>>>(h1h, Wr2h, xr2, NN, 1024, 512);
    dim3 ge2(1024/128, (EE + NN + 127)/128);
    k_hgemm<<<ge2, 256>>>(eah, We2h, ee2, EE + NN, 1024, 16);
    k_node<1024, 2, 32, false><<<NN, 128>>>(xl2, xr2, ee2, att2, b2, nullptr, h2);

    k_lstm<<<(NN + 7)/8, 256>>>(W_ih, b_ih, b_hh, fcW, fcb, out);
}

// round 7
// speedup vs baseline: 4.2587x; 1.0028x over previous
#include <cuda_runtime.h>
#include <cuda_bf16.h>
#include <cstdint>

#define NN 50000
#define EE 500000
#define FIN 388
#define KP1 416    // FIN padded to multiple of 32

typedef __nv_bfloat16 bf16;

// ---------------- static scratch (no allocation allowed) ----------------
__device__ __align__(16) bf16 g_xh  [(size_t)NN*KP1];
__device__ __align__(16) bf16 g_Wl1h[KP1*512];
__device__ __align__(16) bf16 g_Wr1h[KP1*512];
__device__ __align__(16) bf16 g_We1h[32*512];
__device__ __align__(16) bf16 g_xl1 [(size_t)NN*512];
__device__ __align__(16) bf16 g_xr1 [(size_t)NN*512];
__device__ __align__(16) bf16 g_h1h [(size_t)NN*512];
__device__ __align__(16) bf16 g_Wl2h[512*1024];
__device__ __align__(16) bf16 g_Wr2h[512*1024];
__device__ __align__(16) bf16 g_We2h[32*1024];
__device__ __align__(16) bf16 g_xl2 [(size_t)NN*1024];
__device__ __align__(16) bf16 g_xr2 [(size_t)NN*1024];
__device__ __align__(16) bf16 g_eah [(size_t)(EE+NN)*32];
__device__ __align__(16) bf16 g_ee1 [(size_t)(EE+NN)*512];
__device__ __align__(16) bf16 g_ee2 [(size_t)(EE+NN)*1024];

__device__ float g_h2 [(size_t)NN*128];
__device__ float g_loopattr[(size_t)NN*16];
__device__ int   g_cnt[NN];
__device__ int   g_offs[NN+1];
__device__ int   g_cursor[NN];
__device__ int   g_csrsrc[EE];
__device__ int   g_csreid[EE];

// ---------------- conversions to bf16 ----------------
__global__ void k_padcols(const float* __restrict__ in, bf16* __restrict__ out,
                          int ci, int co, long n){
    long t = (long)blockIdx.x * blockDim.x + threadIdx.x;
    if (t >= n * co) return;
    long r = t / co; int c = (int)(t - r * co);
    out[t] = (c < ci) ? __float2bfloat16_rn(in[r * ci + c]) : __float2bfloat16_rn(0.f);
}
__global__ void k_padrows(const float* __restrict__ in, bf16* __restrict__ out,
                          int ri, int ro, int cols){
    int t = blockIdx.x * blockDim.x + threadIdx.x;
    if (t >= ro * cols) return;
    int r = t / cols;
    out[t] = (r < ri) ? __float2bfloat16_rn(in[t]) : __float2bfloat16_rn(0.f);
}

// ---------------- CSR construction ----------------
__global__ void k_cnt(const int* __restrict__ ei){
    int e = blockIdx.x * blockDim.x + threadIdx.x;
    if (e < EE) atomicAdd(&g_cnt[ei[EE + e]], 1);
}

__global__ void k_scan(){
    const int C = (NN + 1023) / 1024;
    int t = threadIdx.x, lane = t & 31, w = t >> 5;
    int s = 0;
    for (int i = 0; i < C; i++){ int idx = t*C + i; if (idx < NN) s += g_cnt[idx]; }
    int v = s;
    #pragma unroll
    for (int o = 1; o < 32; o <<= 1){ int u = __shfl_up_sync(~0u, v, o); if (lane >= o) v += u; }
    __shared__ int ws[32];
    if (lane == 31) ws[w] = v;
    __syncthreads();
    if (w == 0){
        int u2 = ws[lane];
        #pragma unroll
        for (int o = 1; o < 32; o <<= 1){ int u = __shfl_up_sync(~0u, u2, o); if (lane >= o) u2 += u; }
        ws[lane] = u2;
    }
    __syncthreads();
    int pref = v - s + (w > 0 ? ws[w-1] : 0);
    for (int i = 0; i < C; i++){
        int idx = t*C + i;
        if (idx < NN){ g_offs[idx] = pref; g_cursor[idx] = pref; pref += g_cnt[idx]; }
    }
    if (t == 1023) g_offs[NN] = pref;
}

__global__ void k_scatter(const int* __restrict__ ei){
    int e = blockIdx.x * blockDim.x + threadIdx.x;
    if (e >= EE) return;
    int s = ei[e], d = ei[EE + e];
    int pos = atomicAdd(&g_cursor[d], 1);
    g_csrsrc[pos] = s;
    g_csreid[pos] = e;
}

// loop_attr = mean of incoming edge_attr, gathered over CSR (no atomics)
__global__ void k_loopattr(const float* __restrict__ ea){
    int n = blockIdx.x * 8 + (threadIdx.x >> 5);
    if (n >= NN) return;
    int l = threadIdx.x & 31, ep = l >> 4, k = l & 15;
    int e0 = g_offs[n], deg = g_offs[n+1] - e0;
    float s = 0.f;
    for (int e = ep; e < deg; e += 2)
        s += ea[(size_t)g_csreid[e0 + e]*16 + k];
    s += __shfl_xor_sync(~0u, s, 16);
    if (l < 16) g_loopattr[n*16 + l] = s / fmaxf((float)deg, 1.f);
}

// build bf16 edge-attr matrix [(EE+NN)][32] (cols 16..31 zero; rows EE.. = loops)
__global__ void k_eah(const float* __restrict__ ea){
    long t = (long)blockIdx.x * blockDim.x + threadIdx.x;
    if (t >= (long)(EE+NN)*32) return;
    long e = t >> 5; int k = (int)(t & 31);
    float v = 0.f;
    if (k < 16) v = (e < EE) ? ea[e*16 + k] : g_loopattr[(e - EE)*16 + k];
    g_eah[t] = __float2bfloat16_rn(v);
}

// ---------------- bf16 tensor-core GEMM, cp.async 3-stage ----------------
__device__ __forceinline__ void ldsm4(uint32_t* r, const void* p){
    unsigned a = (unsigned)__cvta_generic_to_shared(p);
    asm volatile("ldmatrix.sync.aligned.m8n8.x4.shared.b16 {%0,%1,%2,%3}, [%4];"
      : "=r"(r[0]), "=r"(r[1]), "=r"(r[2]), "=r"(r[3]) : "r"(a));
}
__device__ __forceinline__ void ldsm4t(uint32_t* r, const void* p){
    unsigned a = (unsigned)__cvta_generic_to_shared(p);
    asm volatile("ldmatrix.sync.aligned.m8n8.x4.trans.shared.b16 {%0,%1,%2,%3}, [%4];"
      : "=r"(r[0]), "=r"(r[1]), "=r"(r[2]), "=r"(r[3]) : "r"(a));
}
__device__ __forceinline__ void mma_bf16(float* c, const uint32_t* a, const uint32_t* b){
    asm volatile("mma.sync.aligned.m16n8k16.row.col.f32.bf16.bf16.f32 "
        "{%0,%1,%2,%3}, {%4,%5,%6,%7}, {%8,%9}, {%0,%1,%2,%3};"
        : "+f"(c[0]), "+f"(c[1]), "+f"(c[2]), "+f"(c[3])
        : "r"(a[0]), "r"(a[1]), "r"(a[2]), "r"(a[3]), "r"(b[0]), "r"(b[1]));
}
__device__ __forceinline__ void cpa16(unsigned dst, const void* src, int sz){
    asm volatile("cp.async.cg.shared.global [%0], [%1], 16, %2;"
                 :: "r"(dst), "l"(src), "r"(sz));
}
__device__ __forceinline__ unsigned aswz(unsigned off){   // Swizzle<3,4,3> on 64B rows
    return off ^ (((off >> 7) & 7) << 4);
}

// 128x128x32 tile, 8 warps (64x32 warp tile), 3-stage cp.async pipeline.
__global__ void __launch_bounds__(256, 2)
k_hgemm(const bf16* __restrict__ A, const bf16* __restrict__ B, bf16* __restrict__ C,
        int M, int N, int K)   // K % 32 == 0, N % 128 == 0
{
    // [0,24576): A stages (3 x 8192 B);  [24576,49152): B stages (3 x 8192 B)
    __shared__ __align__(16) char smem_raw[49152];

    const int tid  = threadIdx.x;
    const int lane = tid & 31, warp = tid >> 5;
    const int wm = (warp & 1) * 64;
    const int wn = (warp >> 1) * 32;
    const int bm = blockIdx.y * 128, bn = blockIdx.x * 128;

    // A gmem->smem: thread -> row r = tid>>1, 32B half cc0 = (tid&1)*2 chunks of 16B
    const int a_r = tid >> 1, a_cc0 = (tid & 1) * 2;
    const int gm = bm + a_r;
    const bool aok = (gm < M);
    const bf16* aptr = A + (size_t)(aok ? gm : 0) * K + a_cc0 * 8;
    const int a_sz = aok ? 16 : 0;
    const unsigned a_sw0 = aswz(a_r * 64 + a_cc0 * 16);
    const unsigned a_sw1 = aswz(a_r * 64 + (a_cc0 + 1) * 16);

    // B gmem->smem: row b_r = tid>>3 (0..31), chunks g = (tid&7)*2, +1
    const int b_r = tid >> 3, b_g0 = (tid & 7) * 2;
    const bf16* bptr = B + (size_t)b_r * N + bn + b_g0 * 8;
    const unsigned b_sw0 = (unsigned)(b_r * 256 + ((b_g0     ^ (b_r & 7)) * 16));
    const unsigned b_sw1 = (unsigned)(b_r * 256 + (((b_g0+1) ^ (b_r & 7)) * 16));

    unsigned smem_base = (unsigned)__cvta_generic_to_shared(smem_raw);

    // fragment addressing precompute
    int arow_b[4];
    #pragma unroll
    for (int mt = 0; mt < 4; mt++) arow_b[mt] = (wm + mt*16 + (lane & 15)) * 64;
    const int a_ksel = (lane >> 4);          // 0/1 -> 16B chunk within k16
    const int b_kk_l = lane & 15;
    const int b_ng0  = (wn >> 3) + (lane >> 4);

    float acc[4][4][4];
    #pragma unroll
    for (int i=0;i<4;i++) for (int j=0;j<4;j++) for (int q=0;q<4;q++) acc[i][j][q]=0.f;

    const int niter = K / 32;

    // prologue: issue stages 0..1
    #pragma unroll
    for (int ps = 0; ps < 2; ps++){
        if (ps < niter){
            unsigned as = smem_base + ps * 8192;
            unsigned bs = smem_base + 24576 + ps * 8192;
            int k0 = ps * 32;
            cpa16(as + a_sw0, aptr + k0, a_sz);
            cpa16(as + a_sw1, aptr + k0 + 8, a_sz);
            cpa16(bs + b_sw0, bptr + (size_t)k0 * N, 16);
            cpa16(bs + b_sw1, bptr + (size_t)k0 * N + 8, 16);
        }
        asm volatile("cp.async.commit_group;" ::: "memory");
    }

    for (int it = 0; it < niter; it++){
        asm volatile("cp.async.wait_group 1;" ::: "memory");
        __syncthreads();

        int ldk = it + 2;
        if (ldk < niter){
            int stg = ldk % 3;
            unsigned as = smem_base + stg * 8192;
            unsigned bs = smem_base + 24576 + stg * 8192;
            int k0 = ldk * 32;
            cpa16(as + a_sw0, aptr + k0, a_sz);
            cpa16(as + a_sw1, aptr + k0 + 8, a_sz);
            cpa16(bs + b_sw0, bptr + (size_t)k0 * N, 16);
            cpa16(bs + b_sw1, bptr + (size_t)k0 * N + 8, 16);
        }
        asm volatile("cp.async.commit_group;" ::: "memory");

        int buf = it % 3;
        const char* as = smem_raw + buf * 8192;
        const bf16* bs = (const bf16*)(smem_raw + 24576 + buf * 8192);

        #pragma unroll
        for (int s = 0; s < 2; s++){
            uint32_t af[4][4];
            #pragma unroll
            for (int mt = 0; mt < 4; mt++){
                unsigned off = aswz((unsigned)(arow_b[mt] + (s*2 + a_ksel) * 16));
                ldsm4(af[mt], as + off);
            }
            int kk = s * 16 + b_kk_l;
            uint32_t bfr[2][4];
            #pragma unroll
            for (int p = 0; p < 2; p++){
                int sg = ((b_ng0 + p * 2) ^ (kk & 7));
                ldsm4t(bfr[p], bs + kk * 128 + sg * 8);
            }
            #pragma unroll
            for (int mt = 0; mt < 4; mt++)
                #pragma unroll
                for (int p = 0; p < 2; p++){
                    mma_bf16(acc[mt][p*2+0], af[mt], &bfr[p][0]);
                    mma_bf16(acc[mt][p*2+1], af[mt], &bfr[p][2]);
                }
        }
    }

    // epilogue: write bf16
    #pragma unroll
    for (int mt = 0; mt < 4; mt++) {
        int r0 = bm + wm + mt * 16 + (lane >> 2);
        #pragma unroll
        for (int nt = 0; nt < 4; nt++) {
            int cc = bn + wn + nt * 8 + 2 * (lane & 3);
            if (r0 < M)
                *(__nv_bfloat162*)&C[(size_t)r0 * N + cc] =
                    __floats2bfloat162_rn(acc[mt][nt][0], acc[mt][nt][1]);
            if (r0 + 8 < M)
                *(__nv_bfloat162*)&C[(size_t)(r0 + 8) * N + cc] =
                    __floats2bfloat162_rn(acc[mt][nt][2], acc[mt][nt][3]);
        }
    }
}

// ---------------- fused node-centric GAT layer, online softmax ----------------
// THREADS threads per node; each warp covers 128 contiguous features.
// Thread handles 4 features j = 4*(32*w + l). Scores reduce within REDW lanes.
template<int HD, int THREADS, int REDW, bool CONCAT>
__global__ void __launch_bounds__(THREADS)
k_node(const bf16* __restrict__ xl, const bf16* __restrict__ xr,
       const bf16* __restrict__ ee, const float* __restrict__ att,
       const float* __restrict__ bias, bf16* __restrict__ out_b,
       float* __restrict__ out_f)
{
    const int n = blockIdx.x;
    const int t = threadIdx.x, w = t >> 5, l = t & 31;
    const int q = 32*w + l;   // uint2 index (4 features)

    float xr4[4], at4[4];
    {
        uint2 xv = ((const uint2*)(xr + (size_t)n * HD))[q];
        __nv_bfloat162 p0 = *(__nv_bfloat162*)&xv.x;
        __nv_bfloat162 p1 = *(__nv_bfloat162*)&xv.y;
        xr4[0] = __low2float(p0); xr4[1] = __high2float(p0);
        xr4[2] = __low2float(p1); xr4[3] = __high2float(p1);
        float4 a = *(const float4*)&att[4*q];
        at4[0] = a.x; at4[1] = a.y; at4[2] = a.z; at4[3] = a.w;
    }

    float m = -1e30f, den = 0.f, acc[4] = {0.f, 0.f, 0.f, 0.f};

    const int e0 = g_offs[n];
    const int deg = g_offs[n+1] - e0;

    for (int e = 0; e <= deg; e++){
        int src, eid;
        if (e < deg){ src = g_csrsrc[e0 + e]; eid = g_csreid[e0 + e]; }
        else        { src = n; eid = EE + n; }
        uint2 xv = ((const uint2*)(xl + (size_t)src * HD))[q];
        uint2 ev = ((const uint2*)(ee + (size_t)eid * HD))[q];
        __nv_bfloat162 x0 = *(__nv_bfloat162*)&xv.x;
        __nv_bfloat162 x1 = *(__nv_bfloat162*)&xv.y;
        __nv_bfloat162 e0v = *(__nv_bfloat162*)&ev.x;
        __nv_bfloat162 e1v = *(__nv_bfloat162*)&ev.y;
        float xf[4] = {__low2float(x0), __high2float(x0),
                       __low2float(x1), __high2float(x1)};
        float ef[4] = {__low2float(e0v), __high2float(e0v),
                       __low2float(e1v), __high2float(e1v)};
        float p = 0.f;
        #pragma unroll
        for (int i = 0; i < 4; i++){
            float v = xf[i] + xr4[i] + ef[i];
            v = v > 0.f ? v : 0.2f * v;
            p += at4[i] * v;
        }
        #pragma unroll
        for (int o = REDW/2; o > 0; o >>= 1)
            p += __shfl_xor_sync(~0u, p, o);
        float mn = fmaxf(m, p);
        float sc = __expf(m - mn);
        float pv = __expf(p - mn);
        m = mn;
        den = den * sc + pv;
        #pragma unroll
        for (int i = 0; i < 4; i++)
            acc[i] = acc[i] * sc + pv * xf[i];
    }

    float inv = 1.f / den;
    if (CONCAT){
        __nv_bfloat162* ob = (__nv_bfloat162*)(out_b + (size_t)n * HD);
        float4 b = *(const float4*)&bias[4*q];
        float o0 = tanhf(acc[0]*inv + b.x);
        float o1 = tanhf(acc[1]*inv + b.y);
        float o2 = tanhf(acc[2]*inv + b.z);
        float o3 = tanhf(acc[3]*inv + b.w);
        ob[2*q]     = __floats2bfloat162_rn(o0, o1);
        ob[2*q + 1] = __floats2bfloat162_rn(o2, o3);
    } else {
        // D=128: head = w; d = 4l..4l+3. Mean over 8 heads.
        __shared__ float sm[8][128];
        #pragma unroll
        for (int i = 0; i < 4; i++) sm[w][4*l + i] = acc[i] * inv;
        __syncthreads();
        if (t < 128){
            float s = 0.f;
            #pragma unroll
            for (int h = 0; h < 8; h++) s += sm[h][t];
            out_f[(size_t)n*128 + t] = tanhf(s * 0.125f + bias[t]);
        }
    }
}

// ---------------- single-step LSTM (h0=c0=0) + FC: warp per node ----------------
__global__ void k_lstm(const float* __restrict__ W_ih, const float* __restrict__ b_ih,
                       const float* __restrict__ b_hh, const float* __restrict__ fcW,
                       const float* __restrict__ fcb, float* __restrict__ out)
{
    __shared__ float sh[8][128];
    int w = threadIdx.x >> 5, lane = threadIdx.x & 31;
    int node = blockIdx.x * 8 + w;
    if (node >= NN) return;
    const float* hr = g_h2 + (size_t)node * 128;
    for (int i = lane; i < 128; i += 32) sh[w][i] = hr[i];
    __syncwarp();

    float gates[3];
    const int rows[3] = {lane, 64 + lane, 96 + lane};
    #pragma unroll
    for (int q = 0; q < 3; q++) {
        const float4* wr = (const float4*)(W_ih + (size_t)rows[q] * 128);
        const float4* hv = (const float4*)sh[w];
        float s = 0.f;
        #pragma unroll 8
        for (int k = 0; k < 32; k++) {
            float4 wv = wr[k], xv = hv[k];
            s += wv.x*xv.x + wv.y*xv.y + wv.z*xv.z + wv.w*xv.w;
        }
        gates[q] = s + b_ih[rows[q]] + b_hh[rows[q]];
    }
    float ci = 1.f / (1.f + __expf(-gates[0]));
    float cg = tanhf(gates[1]);
    float co = 1.f / (1.f + __expf(-gates[2]));
    float c  = ci * cg;
    float hid = co * tanhf(c);
    float y = hid * fcW[lane];
    #pragma unroll
    for (int off = 16; off > 0; off >>= 1)
        y += __shfl_xor_sync(0xffffffffu, y, off);
    if (lane == 0) out[node] = y + fcb[0];
}

// ---------------- launch ----------------
extern "C" void kernel_launch(void* const* d_in, const int* in_sizes, int n_in,
                              void* d_out, int out_size)
{
    const float* x    = (const float*)d_in[0];
    const int*   ei   = (const int*)  d_in[1];
    const float* ea   = (const float*)d_in[2];
    const float* Wl1  = (const float*)d_in[3];
    const float* Wr1  = (const float*)d_in[4];
    const float* We1  = (const float*)d_in[5];
    const float* att1 = (const float*)d_in[6];
    const float* b1   = (const float*)d_in[7];
    const float* Wl2  = (const float*)d_in[8];
    const float* Wr2  = (const float*)d_in[9];
    const float* We2  = (const float*)d_in[10];
    const float* att2 = (const float*)d_in[11];
    const float* b2   = (const float*)d_in[12];
    const float* W_ih = (const float*)d_in[13];
    /* d_in[14] = W_hh: unused (h0 = 0) */
    const float* b_ih = (const float*)d_in[15];
    const float* b_hh = (const float*)d_in[16];
    const float* fcW  = (const float*)d_in[17];
    const float* fcb  = (const float*)d_in[18];
    float* out = (float*)d_out;

    void* p;
    bf16 *xh, *Wl1h, *Wr1h, *We1h, *xl1, *xr1, *h1h, *Wl2h, *Wr2h, *We2h, *xl2, *xr2;
    bf16 *eah, *ee1, *ee2;
    int* cnt;
    cudaGetSymbolAddress(&p, g_xh);    xh   = (bf16*)p;
    cudaGetSymbolAddress(&p, g_Wl1h);  Wl1h = (bf16*)p;
    cudaGetSymbolAddress(&p, g_Wr1h);  Wr1h = (bf16*)p;
    cudaGetSymbolAddress(&p, g_We1h);  We1h = (bf16*)p;
    cudaGetSymbolAddress(&p, g_xl1);   xl1  = (bf16*)p;
    cudaGetSymbolAddress(&p, g_xr1);   xr1  = (bf16*)p;
    cudaGetSymbolAddress(&p, g_h1h);   h1h  = (bf16*)p;
    cudaGetSymbolAddress(&p, g_Wl2h);  Wl2h = (bf16*)p;
    cudaGetSymbolAddress(&p, g_Wr2h);  Wr2h = (bf16*)p;
    cudaGetSymbolAddress(&p, g_We2h);  We2h = (bf16*)p;
    cudaGetSymbolAddress(&p, g_xl2);   xl2  = (bf16*)p;
    cudaGetSymbolAddress(&p, g_xr2);   xr2  = (bf16*)p;
    cudaGetSymbolAddress(&p, g_eah);   eah  = (bf16*)p;
    cudaGetSymbolAddress(&p, g_ee1);   ee1  = (bf16*)p;
    cudaGetSymbolAddress(&p, g_ee2);   ee2  = (bf16*)p;
    cudaGetSymbolAddress(&p, g_cnt);   cnt  = (int*)p;
    float* h2; cudaGetSymbolAddress(&p, g_h2); h2 = (float*)p;

    cudaMemsetAsync(cnt, 0, NN * sizeof(int));

    // bf16 conversions for layer-1 GEMMs
    k_padcols<<<(int)(((long)NN*KP1 + 255)/256), 256>>>(x, xh, FIN, KP1, NN);
    k_padrows<<<(KP1*512 + 255)/256, 256>>>(Wl1, Wl1h, FIN, KP1, 512);
    k_padrows<<<(KP1*512 + 255)/256, 256>>>(Wr1, Wr1h, FIN, KP1, 512);
    // CSR counts
    k_cnt<<<(EE + 255)/256, 256>>>(ei);
    // layer-1 node GEMMs
    dim3 g1(512/128, (NN + 127)/128);
    k_hgemm<<<g1, 256>>>(xh, Wl1h, xl1, NN, 512, KP1);
    k_hgemm<<<g1, 256>>>(xh, Wr1h, xr1, NN, 512, KP1);
    // CSR finish + self-loop attrs
    k_scan<<<1, 1024>>>();
    k_scatter<<<(EE + 255)/256, 256>>>(ei);
    k_loopattr<<<(NN + 7)/8, 256>>>(ea);
    k_eah<<<(int)(((long)(EE+NN)*32 + 255)/256), 256>>>(ea);
    // ee1 = eah @ We1   (K = 32)
    k_padrows<<<(32*512 + 255)/256, 256>>>(We1, We1h, 16, 32, 512);
    dim3 ge1(512/128, (EE + NN + 127)/128);
    k_hgemm<<<ge1, 256>>>(eah, We1h, ee1, EE + NN, 512, 32);
    // fused GAT layer 1
    k_node<512, 128, 16, true><<<NN, 128>>>(xl1, xr1, ee1, att1, b1, h1h, nullptr);

    // layer 2
    k_padrows<<<(512*1024 + 255)/256, 256>>>(Wl2, Wl2h, 512, 512, 1024);
    k_padrows<<<(512*1024 + 255)/256, 256>>>(Wr2, Wr2h, 512, 512, 1024);
    k_padrows<<<(32*1024 + 255)/256, 256>>>(We2, We2h, 16, 32, 1024);
    dim3 g2(1024/128, (NN + 127)/128);
    k_hgemm<<<g2, 256>>>(h1h, Wl2h, xl2, NN, 1024, 512);
    k_hgemm<<<g2, 256>>>(h1h, Wr2h, xr2, NN, 1024, 512);
    dim3 ge2(1024/128, (EE + NN + 127)/128);
    k_hgemm<<<ge2, 256>>>(eah, We2h, ee2, EE + NN, 1024, 32);
    k_node<1024, 256, 32, false><<<NN, 256>>>(xl2, xr2, ee2, att2, b2, nullptr, h2);

    k_lstm<<<(NN + 7)/8, 256>>>(W_ih, b_ih, b_hh, fcW, fcb, out);
}

// round 8
// speedup vs baseline: 4.5029x; 1.0573x over previous
#include <cuda_runtime.h>
#include <cuda_bf16.h>
#include <cstdint>

#define NN 50000
#define EE 500000
#define FIN 388
#define KP1 416    // FIN padded to multiple of 32

typedef __nv_bfloat16 bf16;

// ---------------- static scratch (no allocation allowed) ----------------
__device__ __align__(16) bf16 g_xh   [(size_t)NN*KP1];
__device__ __align__(16) bf16 g_Wlr1h[KP1*1024];          // [Wl1 | Wr1]
__device__ __align__(16) bf16 g_We1h [32*512];
__device__ __align__(16) bf16 g_xlr1 [(size_t)NN*1024];   // [xl1 | xr1]
__device__ __align__(16) bf16 g_h1h  [(size_t)NN*512];
__device__ __align__(16) bf16 g_Wlr2h[512*2048];          // [Wl2 | Wr2]
__device__ __align__(16) bf16 g_We2h [32*1024];
__device__ __align__(16) bf16 g_xlr2 [(size_t)NN*2048];   // [xl2 | xr2]
__device__ __align__(16) bf16 g_eah  [(size_t)(EE+NN)*32];
__device__ __align__(16) bf16 g_ee1  [(size_t)(EE+NN)*512];
__device__ __align__(16) bf16 g_ee2  [(size_t)(EE+NN)*1024];

__device__ float g_h2 [(size_t)NN*128];
__device__ float g_loopattr[(size_t)NN*16];
__device__ int   g_cnt[NN];
__device__ int   g_offs[NN+1];
__device__ int   g_cursor[NN];
__device__ int   g_csrsrc[EE];
__device__ int   g_csreid[EE];

// ---------------- conversions to bf16 ----------------
__global__ void k_padcols(const float* __restrict__ in, bf16* __restrict__ out,
                          int ci, int co, long n){
    long t = (long)blockIdx.x * blockDim.x + threadIdx.x;
    if (t >= n * co) return;
    long r = t / co; int c = (int)(t - r * co);
    out[t] = (c < ci) ? __float2bfloat16_rn(in[r * ci + c]) : __float2bfloat16_rn(0.f);
}
__global__ void k_padrows(const float* __restrict__ in, bf16* __restrict__ out,
                          int ri, int ro, int cols){
    int t = blockIdx.x * blockDim.x + threadIdx.x;
    if (t >= ro * cols) return;
    int r = t / cols;
    out[t] = (r < ri) ? __float2bfloat16_rn(in[t]) : __float2bfloat16_rn(0.f);
}
// pack [L | R] side by side: out [ro][2*cols], rows >= ri zero-padded
__global__ void k_pad2(const float* __restrict__ L, const float* __restrict__ R,
                       bf16* __restrict__ out, int ri, int ro, int cols){
    int t = blockIdx.x * blockDim.x + threadIdx.x;
    if (t >= ro * 2 * cols) return;
    int r = t / (2*cols), c = t - r * 2*cols;
    float v = 0.f;
    if (r < ri) v = (c < cols) ? L[r*cols + c] : R[r*cols + (c - cols)];
    out[t] = __float2bfloat16_rn(v);
}

// ---------------- CSR construction ----------------
__global__ void k_cnt(const int* __restrict__ ei){
    int e = blockIdx.x * blockDim.x + threadIdx.x;
    if (e < EE) atomicAdd(&g_cnt[ei[EE + e]], 1);
}

__global__ void k_scan(){
    const int C = (NN + 1023) / 1024;
    int t = threadIdx.x, lane = t & 31, w = t >> 5;
    int s = 0;
    for (int i = 0; i < C; i++){ int idx = t*C + i; if (idx < NN) s += g_cnt[idx]; }
    int v = s;
    #pragma unroll
    for (int o = 1; o < 32; o <<= 1){ int u = __shfl_up_sync(~0u, v, o); if (lane >= o) v += u; }
    __shared__ int ws[32];
    if (lane == 31) ws[w] = v;
    __syncthreads();
    if (w == 0){
        int u2 = ws[lane];
        #pragma unroll
        for (int o = 1; o < 32; o <<= 1){ int u = __shfl_up_sync(~0u, u2, o); if (lane >= o) u2 += u; }
        ws[lane] = u2;
    }
    __syncthreads();
    int pref = v - s + (w > 0 ? ws[w-1] : 0);
    for (int i = 0; i < C; i++){
        int idx = t*C + i;
        if (idx < NN){ g_offs[idx] = pref; g_cursor[idx] = pref; pref += g_cnt[idx]; }
    }
    if (t == 1023) g_offs[NN] = pref;
}

__global__ void k_scatter(const int* __restrict__ ei){
    int e = blockIdx.x * blockDim.x + threadIdx.x;
    if (e >= EE) return;
    int s = ei[e], d = ei[EE + e];
    int pos = atomicAdd(&g_cursor[d], 1);
    g_csrsrc[pos] = s;
    g_csreid[pos] = e;
}

// loop_attr = mean of incoming edge_attr, gathered over CSR (no atomics)
__global__ void k_loopattr(const float* __restrict__ ea){
    int n = blockIdx.x * 8 + (threadIdx.x >> 5);
    if (n >= NN) return;
    int l = threadIdx.x & 31, ep = l >> 4, k = l & 15;
    int e0 = g_offs[n], deg = g_offs[n+1] - e0;
    float s = 0.f;
    for (int e = ep; e < deg; e += 2)
        s += ea[(size_t)g_csreid[e0 + e]*16 + k];
    s += __shfl_xor_sync(~0u, s, 16);
    if (l < 16) g_loopattr[n*16 + l] = s / fmaxf((float)deg, 1.f);
}

// build bf16 edge-attr matrix [(EE+NN)][32] (cols 16..31 zero; rows EE.. = loops)
__global__ void k_eah(const float* __restrict__ ea){
    long t = (long)blockIdx.x * blockDim.x + threadIdx.x;
    if (t >= (long)(EE+NN)*32) return;
    long e = t >> 5; int k = (int)(t & 31);
    float v = 0.f;
    if (k < 16) v = (e < EE) ? ea[e*16 + k] : g_loopattr[(e - EE)*16 + k];
    g_eah[t] = __float2bfloat16_rn(v);
}

// ---------------- bf16 tensor-core GEMM, cp.async 3-stage ----------------
__device__ __forceinline__ void ldsm4(uint32_t* r, const void* p){
    unsigned a = (unsigned)__cvta_generic_to_shared(p);
    asm volatile("ldmatrix.sync.aligned.m8n8.x4.shared.b16 {%0,%1,%2,%3}, [%4];"
      : "=r"(r[0]), "=r"(r[1]), "=r"(r[2]), "=r"(r[3]) : "r"(a));
}
__device__ __forceinline__ void ldsm4t(uint32_t* r, const void* p){
    unsigned a = (unsigned)__cvta_generic_to_shared(p);
    asm volatile("ldmatrix.sync.aligned.m8n8.x4.trans.shared.b16 {%0,%1,%2,%3}, [%4];"
      : "=r"(r[0]), "=r"(r[1]), "=r"(r[2]), "=r"(r[3]) : "r"(a));
}
__device__ __forceinline__ void mma_bf16(float* c, const uint32_t* a, const uint32_t* b){
    asm volatile("mma.sync.aligned.m16n8k16.row.col.f32.bf16.bf16.f32 "
        "{%0,%1,%2,%3}, {%4,%5,%6,%7}, {%8,%9}, {%0,%1,%2,%3};"
        : "+f"(c[0]), "+f"(c[1]), "+f"(c[2]), "+f"(c[3])
        : "r"(a[0]), "r"(a[1]), "r"(a[2]), "r"(a[3]), "r"(b[0]), "r"(b[1]));
}
__device__ __forceinline__ void cpa16(unsigned dst, const void* src, int sz){
    asm volatile("cp.async.cg.shared.global [%0], [%1], 16, %2;"
                 :: "r"(dst), "l"(src), "r"(sz));
}
__device__ __forceinline__ unsigned aswz(unsigned off){   // Swizzle<3,4,3> on 64B rows
    return off ^ (((off >> 7) & 7) << 4);
}

// 128x128x32 tile, 8 warps (64x32 warp tile), 3-stage cp.async pipeline.
__global__ void __launch_bounds__(256, 2)
k_hgemm(const bf16* __restrict__ A, const bf16* __restrict__ B, bf16* __restrict__ C,
        int M, int N, int K)   // K % 32 == 0, N % 128 == 0
{
    __shared__ __align__(16) char smem_raw[49152];

    const int tid  = threadIdx.x;
    const int lane = tid & 31, warp = tid >> 5;
    const int wm = (warp & 1) * 64;
    const int wn = (warp >> 1) * 32;
    const int bm = blockIdx.y * 128, bn = blockIdx.x * 128;

    const int a_r = tid >> 1, a_cc0 = (tid & 1) * 2;
    const int gm = bm + a_r;
    const bool aok = (gm < M);
    const bf16* aptr = A + (size_t)(aok ? gm : 0) * K + a_cc0 * 8;
    const int a_sz = aok ? 16 : 0;
    const unsigned a_sw0 = aswz(a_r * 64 + a_cc0 * 16);
    const unsigned a_sw1 = aswz(a_r * 64 + (a_cc0 + 1) * 16);

    const int b_r = tid >> 3, b_g0 = (tid & 7) * 2;
    const bf16* bptr = B + (size_t)b_r * N + bn + b_g0 * 8;
    const unsigned b_sw0 = (unsigned)(b_r * 256 + ((b_g0     ^ (b_r & 7)) * 16));
    const unsigned b_sw1 = (unsigned)(b_r * 256 + (((b_g0+1) ^ (b_r & 7)) * 16));

    unsigned smem_base = (unsigned)__cvta_generic_to_shared(smem_raw);

    int arow_b[4];
    #pragma unroll
    for (int mt = 0; mt < 4; mt++) arow_b[mt] = (wm + mt*16 + (lane & 15)) * 64;
    const int a_ksel = (lane >> 4);
    const int b_kk_l = lane & 15;
    const int b_ng0  = (wn >> 3) + (lane >> 4);

    float acc[4][4][4];
    #pragma unroll
    for (int i=0;i<4;i++) for (int j=0;j<4;j++) for (int q=0;q<4;q++) acc[i][j][q]=0.f;

    const int niter = K / 32;

    #pragma unroll
    for (int ps = 0; ps < 2; ps++){
        if (ps < niter){
            unsigned as = smem_base + ps * 8192;
            unsigned bs = smem_base + 24576 + ps * 8192;
            int k0 = ps * 32;
            cpa16(as + a_sw0, aptr + k0, a_sz);
            cpa16(as + a_sw1, aptr + k0 + 8, a_sz);
            cpa16(bs + b_sw0, bptr + (size_t)k0 * N, 16);
            cpa16(bs + b_sw1, bptr + (size_t)k0 * N + 8, 16);
        }
        asm volatile("cp.async.commit_group;" ::: "memory");
    }

    for (int it = 0; it < niter; it++){
        asm volatile("cp.async.wait_group 1;" ::: "memory");
        __syncthreads();

        int ldk = it + 2;
        if (ldk < niter){
            int stg = ldk % 3;
            unsigned as = smem_base + stg * 8192;
            unsigned bs = smem_base + 24576 + stg * 8192;
            int k0 = ldk * 32;
            cpa16(as + a_sw0, aptr + k0, a_sz);
            cpa16(as + a_sw1, aptr + k0 + 8, a_sz);
            cpa16(bs + b_sw0, bptr + (size_t)k0 * N, 16);
            cpa16(bs + b_sw1, bptr + (size_t)k0 * N + 8, 16);
        }
        asm volatile("cp.async.commit_group;" ::: "memory");

        int buf = it % 3;
        const char* as = smem_raw + buf * 8192;
        const bf16* bs = (const bf16*)(smem_raw + 24576 + buf * 8192);

        #pragma unroll
        for (int s = 0; s < 2; s++){
            uint32_t af[4][4];
            #pragma unroll
            for (int mt = 0; mt < 4; mt++){
                unsigned off = aswz((unsigned)(arow_b[mt] + (s*2 + a_ksel) * 16));
                ldsm4(af[mt], as + off);
            }
            int kk = s * 16 + b_kk_l;
            uint32_t bfr[2][4];
            #pragma unroll
            for (int p = 0; p < 2; p++){
                int sg = ((b_ng0 + p * 2) ^ (kk & 7));
                ldsm4t(bfr[p], bs + kk * 128 + sg * 8);
            }
            #pragma unroll
            for (int mt = 0; mt < 4; mt++)
                #pragma unroll
                for (int p = 0; p < 2; p++){
                    mma_bf16(acc[mt][p*2+0], af[mt], &bfr[p][0]);
                    mma_bf16(acc[mt][p*2+1], af[mt], &bfr[p][2]);
                }
        }
    }

    #pragma unroll
    for (int mt = 0; mt < 4; mt++) {
        int r0 = bm + wm + mt * 16 + (lane >> 2);
        #pragma unroll
        for (int nt = 0; nt < 4; nt++) {
            int cc = bn + wn + nt * 8 + 2 * (lane & 3);
            if (r0 < M)
                *(__nv_bfloat162*)&C[(size_t)r0 * N + cc] =
                    __floats2bfloat162_rn(acc[mt][nt][0], acc[mt][nt][1]);
            if (r0 + 8 < M)
                *(__nv_bfloat162*)&C[(size_t)(r0 + 8) * N + cc] =
                    __floats2bfloat162_rn(acc[mt][nt][2], acc[mt][nt][3]);
        }
    }
}

// ---------------- fused node-centric GAT layer, online softmax ----------------
// xlr rows are [xl | xr] with stride 2*HD. Thread handles 4 features j=4q..4q+3.
// Software pipeline: src/eid prefetched 2 edges ahead, gathers 1 edge ahead.
template<int HD, int THREADS, int REDW, bool CONCAT>
__global__ void __launch_bounds__(THREADS)
k_node(const bf16* __restrict__ xlr, const bf16* __restrict__ ee,
       const float* __restrict__ att, const float* __restrict__ bias,
       bf16* __restrict__ out_b, float* __restrict__ out_f)
{
    const int n = blockIdx.x;
    const int t = threadIdx.x, w = t >> 5, l = t & 31;
    const int q = 32*w + l;   // uint2 index (4 features)

    float xr4[4], at4[4];
    {
        uint2 xv = ((const uint2*)(xlr + (size_t)n * (2*HD) + HD))[q];
        __nv_bfloat162 p0 = *(__nv_bfloat162*)&xv.x;
        __nv_bfloat162 p1 = *(__nv_bfloat162*)&xv.y;
        xr4[0] = __low2float(p0); xr4[1] = __high2float(p0);
        xr4[2] = __low2float(p1); xr4[3] = __high2float(p1);
        float4 a = *(const float4*)&att[4*q];
        at4[0] = a.x; at4[1] = a.y; at4[2] = a.z; at4[3] = a.w;
    }

    float m = -1e30f, den = 0.f, acc[4] = {0.f, 0.f, 0.f, 0.f};

    const int e0 = g_offs[n];
    const int deg = g_offs[n+1] - e0;

    // prefetch pipeline
    int s1 = (0 < deg) ? g_csrsrc[e0] : n;
    int i1 = (0 < deg) ? g_csreid[e0] : (EE + n);
    uint2 xv1 = ((const uint2*)(xlr + (size_t)s1 * (2*HD)))[q];
    uint2 ev1 = ((const uint2*)(ee  + (size_t)i1 * HD))[q];
    int s2 = (1 < deg) ? g_csrsrc[e0 + 1] : n;
    int i2 = (1 < deg) ? g_csreid[e0 + 1] : (EE + n);

    for (int e = 0; e <= deg; e++){
        uint2 xv2, ev2;
        if (e + 1 <= deg){
            xv2 = ((const uint2*)(xlr + (size_t)s2 * (2*HD)))[q];
            ev2 = ((const uint2*)(ee  + (size_t)i2 * HD))[q];
        }
        int s3 = (e + 2 < deg) ? g_csrsrc[e0 + e + 2] : n;
        int i3 = (e + 2 < deg) ? g_csreid[e0 + e + 2] : (EE + n);

        __nv_bfloat162 x0 = *(__nv_bfloat162*)&xv1.x;
        __nv_bfloat162 x1 = *(__nv_bfloat162*)&xv1.y;
        __nv_bfloat162 e0v = *(__nv_bfloat162*)&ev1.x;
        __nv_bfloat162 e1v = *(__nv_bfloat162*)&ev1.y;
        float xf[4] = {__low2float(x0), __high2float(x0),
                       __low2float(x1), __high2float(x1)};
        float ef[4] = {__low2float(e0v), __high2float(e0v),
                       __low2float(e1v), __high2float(e1v)};
        float p = 0.f;
        #pragma unroll
        for (int i = 0; i < 4; i++){
            float v = xf[i] + xr4[i] + ef[i];
            v = v > 0.f ? v : 0.2f * v;
            p += at4[i] * v;
        }
        #pragma unroll
        for (int o = REDW/2; o > 0; o >>= 1)
            p += __shfl_xor_sync(~0u, p, o);
        float mn = fmaxf(m, p);
        float sc = __expf(m - mn);
        float pv = __expf(p - mn);
        m = mn;
        den = den * sc + pv;
        #pragma unroll
        for (int i = 0; i < 4; i++)
            acc[i] = acc[i] * sc + pv * xf[i];

        xv1 = xv2; ev1 = ev2; s2 = s3; i2 = i3;
    }

    float inv = 1.f / den;
    if (CONCAT){
        __nv_bfloat162* ob = (__nv_bfloat162*)(out_b + (size_t)n * HD);
        float4 b = *(const float4*)&bias[4*q];
        float o0 = tanhf(acc[0]*inv + b.x);
        float o1 = tanhf(acc[1]*inv + b.y);
        float o2 = tanhf(acc[2]*inv + b.z);
        float o3 = tanhf(acc[3]*inv + b.w);
        ob[2*q]     = __floats2bfloat162_rn(o0, o1);
        ob[2*q + 1] = __floats2bfloat162_rn(o2, o3);
    } else {
        __shared__ float sm[8][128];
        #pragma unroll
        for (int i = 0; i < 4; i++) sm[w][4*l + i] = acc[i] * inv;
        __syncthreads();
        if (t < 128){
            float s = 0.f;
            #pragma unroll
            for (int h = 0; h < 8; h++) s += sm[h][t];
            out_f[(size_t)n*128 + t] = tanhf(s * 0.125f + bias[t]);
        }
    }
}

// ---------------- single-step LSTM (h0=c0=0) + FC: warp per node ----------------
__global__ void k_lstm(const float* __restrict__ W_ih, const float* __restrict__ b_ih,
                       const float* __restrict__ b_hh, const float* __restrict__ fcW,
                       const float* __restrict__ fcb, float* __restrict__ out)
{
    __shared__ float sh[8][128];
    int w = threadIdx.x >> 5, lane = threadIdx.x & 31;
    int node = blockIdx.x * 8 + w;
    if (node >= NN) return;
    const float* hr = g_h2 + (size_t)node * 128;
    for (int i = lane; i < 128; i += 32) sh[w][i] = hr[i];
    __syncwarp();

    float gates[3];
    const int rows[3] = {lane, 64 + lane, 96 + lane};
    #pragma unroll
    for (int q = 0; q < 3; q++) {
        const float4* wr = (const float4*)(W_ih + (size_t)rows[q] * 128);
        const float4* hv = (const float4*)sh[w];
        float s = 0.f;
        #pragma unroll 8
        for (int k = 0; k < 32; k++) {
            float4 wv = wr[k], xv = hv[k];
            s += wv.x*xv.x + wv.y*xv.y + wv.z*xv.z + wv.w*xv.w;
        }
        gates[q] = s + b_ih[rows[q]] + b_hh[rows[q]];
    }
    float ci = 1.f / (1.f + __expf(-gates[0]));
    float cg = tanhf(gates[1]);
    float co = 1.f / (1.f + __expf(-gates[2]));
    float c  = ci * cg;
    float hid = co * tanhf(c);
    float y = hid * fcW[lane];
    #pragma unroll
    for (int off = 16; off > 0; off >>= 1)
        y += __shfl_xor_sync(0xffffffffu, y, off);
    if (lane == 0) out[node] = y + fcb[0];
}

// ---------------- launch ----------------
extern "C" void kernel_launch(void* const* d_in, const int* in_sizes, int n_in,
                              void* d_out, int out_size)
{
    const float* x    = (const float*)d_in[0];
    const int*   ei   = (const int*)  d_in[1];
    const float* ea   = (const float*)d_in[2];
    const float* Wl1  = (const float*)d_in[3];
    const float* Wr1  = (const float*)d_in[4];
    const float* We1  = (const float*)d_in[5];
    const float* att1 = (const float*)d_in[6];
    const float* b1   = (const float*)d_in[7];
    const float* Wl2  = (const float*)d_in[8];
    const float* Wr2  = (const float*)d_in[9];
    const float* We2  = (const float*)d_in[10];
    const float* att2 = (const float*)d_in[11];
    const float* b2   = (const float*)d_in[12];
    const float* W_ih = (const float*)d_in[13];
    /* d_in[14] = W_hh: unused (h0 = 0) */
    const float* b_ih = (const float*)d_in[15];
    const float* b_hh = (const float*)d_in[16];
    const float* fcW  = (const float*)d_in[17];
    const float* fcb  = (const float*)d_in[18];
    float* out = (float*)d_out;

    void* p;
    bf16 *xh, *Wlr1h, *We1h, *xlr1, *h1h, *Wlr2h, *We2h, *xlr2, *eah, *ee1, *ee2;
    int* cnt;
    cudaGetSymbolAddress(&p, g_xh);     xh    = (bf16*)p;
    cudaGetSymbolAddress(&p, g_Wlr1h);  Wlr1h = (bf16*)p;
    cudaGetSymbolAddress(&p, g_We1h);   We1h  = (bf16*)p;
    cudaGetSymbolAddress(&p, g_xlr1);   xlr1  = (bf16*)p;
    cudaGetSymbolAddress(&p, g_h1h);    h1h   = (bf16*)p;
    cudaGetSymbolAddress(&p, g_Wlr2h);  Wlr2h = (bf16*)p;
    cudaGetSymbolAddress(&p, g_We2h);   We2h  = (bf16*)p;
    cudaGetSymbolAddress(&p, g_xlr2);   xlr2  = (bf16*)p;
    cudaGetSymbolAddress(&p, g_eah);    eah   = (bf16*)p;
    cudaGetSymbolAddress(&p, g_ee1);    ee1   = (bf16*)p;
    cudaGetSymbolAddress(&p, g_ee2);    ee2   = (bf16*)p;
    cudaGetSymbolAddress(&p, g_cnt);    cnt   = (int*)p;
    float* h2; cudaGetSymbolAddress(&p, g_h2); h2 = (float*)p;

    cudaMemsetAsync(cnt, 0, NN * sizeof(int));

    // kernels 1-3
    k_padcols<<<(int)(((long)NN*KP1 + 255)/256), 256>>>(x, xh, FIN, KP1, NN);
    k_pad2<<<(KP1*1024 + 255)/256, 256>>>(Wl1, Wr1, Wlr1h, FIN, KP1, 512);
    k_cnt<<<(EE + 255)/256, 256>>>(ei);
    // kernel 4: merged layer-1 GEMM (ncu capture slot)
    dim3 g1(1024/128, (NN + 127)/128);
    k_hgemm<<<g1, 256>>>(xh, Wlr1h, xlr1, NN, 1024, KP1);
    // CSR finish + self-loop attrs
    k_scan<<<1, 1024>>>();
    k_scatter<<<(EE + 255)/256, 256>>>(ei);
    k_loopattr<<<(NN + 7)/8, 256>>>(ea);
    k_eah<<<(int)(((long)(EE+NN)*32 + 255)/256), 256>>>(ea);
    // ee1 = eah @ We1   (K = 32)
    k_padrows<<<(32*512 + 255)/256, 256>>>(We1, We1h, 16, 32, 512);
    dim3 ge1(512/128, (EE + NN + 127)/128);
    k_hgemm<<<ge1, 256>>>(eah, We1h, ee1, EE + NN, 512, 32);
    // fused GAT layer 1
    k_node<512, 128, 16, true><<<NN, 128>>>(xlr1, ee1, att1, b1, h1h, nullptr);

    // layer 2
    k_pad2<<<(512*2048 + 255)/256, 256>>>(Wl2, Wr2, Wlr2h, 512, 512, 1024);
    dim3 g2(2048/128, (NN + 127)/128);
    k_hgemm<<<g2, 256>>>(h1h, Wlr2h, xlr2, NN, 2048, 512);
    k_padrows<<<(32*1024 + 255)/256, 256>>>(We2, We2h, 16, 32, 1024);
    dim3 ge2(1024/128, (EE + NN + 127)/128);
    k_hgemm<<<ge2, 256>>>(eah, We2h, ee2, EE + NN, 1024, 32);
    k_node<1024, 256, 32, false><<<NN, 256>>>(xlr2, ee2, att2, b2, nullptr, h2);

    k_lstm<<<(NN + 7)/8, 256>>>(W_ih, b_ih, b_hh, fcW, fcb, out);
}